// round 1
// baseline (speedup 1.0000x reference)
#include <cuda_runtime.h>
#include <math.h>

#define BDIM 4
#define SDIM 2048
#define IDIM 1024
#define DDIM 1024

// Scratch (allocation-free rule: __device__ globals)
__device__ float g_qp[(size_t)BDIM * SDIM * DDIM];      // 32 MB
__device__ float g_kp[(size_t)BDIM * SDIM * DDIM];      // 32 MB
__device__ float g_vp[(size_t)BDIM * SDIM * DDIM];      // 32 MB
__device__ float g_logits[(size_t)BDIM * SDIM * SDIM];  // 64 MB

// ---------------------------------------------------------------------------
// Generic 128x128 fp32 GEMM, BK=8, 256 threads, 8x8 per-thread register tile.
// TRANS_B=false: C = A[MxK] * B[KxN]      (B row-major [K,N])
// TRANS_B=true : C = A[MxK] * B^T         (B row-major [N,K])
// blockIdx.z batches via sA/sB/sC element strides.
// ---------------------------------------------------------------------------
template <bool TRANS_B, bool ADD_BIAS>
__global__ void __launch_bounds__(256)
gemm128(const float* __restrict__ Ag, const float* __restrict__ Bg,
        const float* __restrict__ bias, float* __restrict__ Cg,
        int M, int N, int K, size_t sA, size_t sB, size_t sC)
{
    __shared__ float As[8][128];
    __shared__ float Bs[8][128];

    const float* A = Ag + (size_t)blockIdx.z * sA;
    const float* Bp = Bg + (size_t)blockIdx.z * sB;
    float* C = Cg + (size_t)blockIdx.z * sC;

    const int tid = threadIdx.x;
    const int tx = tid & 15;   // N direction (16)
    const int ty = tid >> 4;   // M direction (16)
    const int rowBase = blockIdx.y * 128;
    const int colBase = blockIdx.x * 128;

    // Transposed-tile loader indices (used for A always, B when TRANS_B)
    const int lRow = tid >> 1;        // 0..127
    const int lCol = (tid & 1) * 4;   // 0 or 4
    // NN B loader indices
    const int bRow = tid >> 5;        // 0..7
    const int bCol = (tid & 31) * 4;  // 0..124

    float acc[8][8];
#pragma unroll
    for (int i = 0; i < 8; i++)
#pragma unroll
        for (int j = 0; j < 8; j++) acc[i][j] = 0.f;

    for (int kt = 0; kt < K; kt += 8) {
        float4 a4 = *(const float4*)(A + (size_t)(rowBase + lRow) * K + kt + lCol);
        As[lCol + 0][lRow] = a4.x;
        As[lCol + 1][lRow] = a4.y;
        As[lCol + 2][lRow] = a4.z;
        As[lCol + 3][lRow] = a4.w;
        if (TRANS_B) {
            float4 b4 = *(const float4*)(Bp + (size_t)(colBase + lRow) * K + kt + lCol);
            Bs[lCol + 0][lRow] = b4.x;
            Bs[lCol + 1][lRow] = b4.y;
            Bs[lCol + 2][lRow] = b4.z;
            Bs[lCol + 3][lRow] = b4.w;
        } else {
            *(float4*)&Bs[bRow][bCol] =
                *(const float4*)(Bp + (size_t)(kt + bRow) * N + colBase + bCol);
        }
        __syncthreads();
#pragma unroll
        for (int kk = 0; kk < 8; kk++) {
            float ra[8], rb[8];
            *(float4*)&ra[0] = *(const float4*)&As[kk][ty * 4];
            *(float4*)&ra[4] = *(const float4*)&As[kk][ty * 4 + 64];
            *(float4*)&rb[0] = *(const float4*)&Bs[kk][tx * 4];
            *(float4*)&rb[4] = *(const float4*)&Bs[kk][tx * 4 + 64];
#pragma unroll
            for (int i = 0; i < 8; i++)
#pragma unroll
                for (int j = 0; j < 8; j++)
                    acc[i][j] = fmaf(ra[i], rb[j], acc[i][j]);
        }
        __syncthreads();
    }

#pragma unroll
    for (int ih = 0; ih < 2; ih++) {
#pragma unroll
        for (int ii = 0; ii < 4; ii++) {
            size_t r = (size_t)(rowBase + ih * 64 + ty * 4 + ii);
#pragma unroll
            for (int jh = 0; jh < 2; jh++) {
                int c = colBase + jh * 64 + tx * 4;
                float4 o;
                o.x = acc[ih * 4 + ii][jh * 4 + 0];
                o.y = acc[ih * 4 + ii][jh * 4 + 1];
                o.z = acc[ih * 4 + ii][jh * 4 + 2];
                o.w = acc[ih * 4 + ii][jh * 4 + 3];
                if (ADD_BIAS) {
                    o.x += bias[c + 0];
                    o.y += bias[c + 1];
                    o.z += bias[c + 2];
                    o.w += bias[c + 3];
                }
                *(float4*)(C + r * (size_t)N + c) = o;
            }
        }
    }
}

// ---------------------------------------------------------------------------
// Fused scale + mask + row softmax. One block per row (B*S rows, S cols).
// ---------------------------------------------------------------------------
__global__ void __launch_bounds__(256)
softmax_kernel(float* __restrict__ logits, const float* __restrict__ mask,
               float scale)
{
    __shared__ float red[8];
    __shared__ float bval;

    size_t row = blockIdx.x;
    int q = (int)(row & (SDIM - 1));  // row % S (S power of 2)
    float* rp = logits + row * (size_t)SDIM;
    const float* mp = mask + (size_t)q * SDIM;
    int t = threadIdx.x;

    float4 a = ((const float4*)rp)[t];
    float4 b = ((const float4*)rp)[t + 256];
    float4 ma = ((const float4*)mp)[t];
    float4 mb = ((const float4*)mp)[t + 256];
    float x[8];
    x[0] = fmaf(a.x, scale, ma.x);
    x[1] = fmaf(a.y, scale, ma.y);
    x[2] = fmaf(a.z, scale, ma.z);
    x[3] = fmaf(a.w, scale, ma.w);
    x[4] = fmaf(b.x, scale, mb.x);
    x[5] = fmaf(b.y, scale, mb.y);
    x[6] = fmaf(b.z, scale, mb.z);
    x[7] = fmaf(b.w, scale, mb.w);

    float mx = x[0];
#pragma unroll
    for (int i = 1; i < 8; i++) mx = fmaxf(mx, x[i]);
#pragma unroll
    for (int o = 16; o; o >>= 1) mx = fmaxf(mx, __shfl_xor_sync(0xffffffffu, mx, o));
    if ((t & 31) == 0) red[t >> 5] = mx;
    __syncthreads();
    if (t == 0) {
        float m = red[0];
#pragma unroll
        for (int i = 1; i < 8; i++) m = fmaxf(m, red[i]);
        bval = m;
    }
    __syncthreads();
    mx = bval;

    float s = 0.f;
#pragma unroll
    for (int i = 0; i < 8; i++) {
        x[i] = __expf(x[i] - mx);
        s += x[i];
    }
#pragma unroll
    for (int o = 16; o; o >>= 1) s += __shfl_xor_sync(0xffffffffu, s, o);
    if ((t & 31) == 0) red[t >> 5] = s;
    __syncthreads();
    if (t == 0) {
        float ss = 0.f;
#pragma unroll
        for (int i = 0; i < 8; i++) ss += red[i];
        bval = 1.f / ss;
    }
    __syncthreads();
    float inv = bval;

    a.x = x[0] * inv; a.y = x[1] * inv; a.z = x[2] * inv; a.w = x[3] * inv;
    b.x = x[4] * inv; b.y = x[5] * inv; b.z = x[6] * inv; b.w = x[7] * inv;
    ((float4*)rp)[t] = a;
    ((float4*)rp)[t + 256] = b;
}

extern "C" void kernel_launch(void* const* d_in, const int* in_sizes, int n_in,
                              void* d_out, int out_size)
{
    const float* q    = (const float*)d_in[0];
    const float* k    = (const float*)d_in[1];
    const float* v    = (const float*)d_in[2];
    const float* mask = (const float*)d_in[3];
    const float* wq   = (const float*)d_in[4];
    const float* bq   = (const float*)d_in[5];
    const float* wk   = (const float*)d_in[6];
    const float* bk   = (const float*)d_in[7];
    const float* wv   = (const float*)d_in[8];
    const float* bv   = (const float*)d_in[9];
    float* out = (float*)d_out;

    float *qp, *kp, *vp, *lg;
    cudaGetSymbolAddress((void**)&qp, g_qp);
    cudaGetSymbolAddress((void**)&kp, g_kp);
    cudaGetSymbolAddress((void**)&vp, g_vp);
    cudaGetSymbolAddress((void**)&lg, g_logits);

    dim3 blk(256);

    // QKV projections: [8192,1024] @ [1024,1024] + bias
    dim3 gp(DDIM / 128, (BDIM * SDIM) / 128, 1);
    gemm128<false, true><<<gp, blk>>>(q, wq, bq, qp, BDIM * SDIM, DDIM, IDIM, 0, 0, 0);
    gemm128<false, true><<<gp, blk>>>(k, wk, bk, kp, BDIM * SDIM, DDIM, IDIM, 0, 0, 0);
    gemm128<false, true><<<gp, blk>>>(v, wv, bv, vp, BDIM * SDIM, DDIM, IDIM, 0, 0, 0);

    // logits = qp @ kp^T, batched over B
    dim3 gl(SDIM / 128, SDIM / 128, BDIM);
    gemm128<true, false><<<gl, blk>>>(qp, kp, nullptr, lg, SDIM, SDIM, DDIM,
                                      (size_t)SDIM * DDIM, (size_t)SDIM * DDIM,
                                      (size_t)SDIM * SDIM);

    // softmax(logits * 1/sqrt(D) + mask)
    softmax_kernel<<<BDIM * SDIM, blk>>>(lg, mask, 0.03125f);

    // out = attn @ vp, batched over B
    dim3 ga(DDIM / 128, SDIM / 128, BDIM);
    gemm128<false, false><<<ga, blk>>>(lg, vp, nullptr, out, SDIM, DDIM, SDIM,
                                       (size_t)SDIM * SDIM, (size_t)SDIM * DDIM,
                                       (size_t)SDIM * DDIM);
}

// round 3
// speedup vs baseline: 2.1291x; 2.1291x over previous
#include <cuda_runtime.h>
#include <cuda_bf16.h>
#include <cstdint>

#define BDIM 4
#define SDIM 2048
#define IDIM 1024
#define DDIM 1024
#define NTOK (BDIM * SDIM)   // 8192

// ---------------------------------------------------------------------------
// Device scratch (allocation-free rule)
// ---------------------------------------------------------------------------
__device__ __align__(128) __nv_bfloat16 g_qh[(size_t)NTOK * IDIM];
__device__ __align__(128) __nv_bfloat16 g_ql[(size_t)NTOK * IDIM];
__device__ __align__(128) __nv_bfloat16 g_kh[(size_t)NTOK * IDIM];
__device__ __align__(128) __nv_bfloat16 g_kl[(size_t)NTOK * IDIM];
__device__ __align__(128) __nv_bfloat16 g_vh[(size_t)NTOK * IDIM];
__device__ __align__(128) __nv_bfloat16 g_vl[(size_t)NTOK * IDIM];
__device__ __align__(128) __nv_bfloat16 g_wqt_h[(size_t)DDIM * IDIM];
__device__ __align__(128) __nv_bfloat16 g_wqt_l[(size_t)DDIM * IDIM];
__device__ __align__(128) __nv_bfloat16 g_wkt_h[(size_t)DDIM * IDIM];
__device__ __align__(128) __nv_bfloat16 g_wkt_l[(size_t)DDIM * IDIM];
__device__ __align__(128) __nv_bfloat16 g_wvt_h[(size_t)DDIM * IDIM];
__device__ __align__(128) __nv_bfloat16 g_wvt_l[(size_t)DDIM * IDIM];
__device__ __align__(128) __nv_bfloat16 g_qph[(size_t)NTOK * DDIM];
__device__ __align__(128) __nv_bfloat16 g_qpl[(size_t)NTOK * DDIM];
__device__ __align__(128) __nv_bfloat16 g_kph[(size_t)NTOK * DDIM];
__device__ __align__(128) __nv_bfloat16 g_kpl[(size_t)NTOK * DDIM];
__device__ __align__(128) __nv_bfloat16 g_vpth[(size_t)DDIM * NTOK];  // [D, tokens]
__device__ __align__(128) __nv_bfloat16 g_vptl[(size_t)DDIM * NTOK];
__device__ __align__(128) float g_logits[(size_t)BDIM * SDIM * SDIM];
__device__ __align__(128) __nv_bfloat16 g_ah[(size_t)BDIM * SDIM * SDIM];
__device__ __align__(128) __nv_bfloat16 g_al[(size_t)BDIM * SDIM * SDIM];

// ---------------------------------------------------------------------------
// PTX helpers (no tcgen05 — harness compiles for compute_103 w/o 'a' features)
// ---------------------------------------------------------------------------
__device__ __forceinline__ uint32_t smem_u32(const void* p) {
    uint32_t a;
    asm("{ .reg .u64 t; cvta.to.shared.u64 t, %1; cvt.u32.u64 %0, t; }"
        : "=r"(a) : "l"(p));
    return a;
}

__device__ __forceinline__ void cp16(uint32_t d, const void* g) {
    asm volatile("cp.async.cg.shared.global [%0], [%1], 16;" :: "r"(d), "l"(g) : "memory");
}
#define CP_COMMIT() asm volatile("cp.async.commit_group;" ::: "memory")
#define CP_WAIT0()  asm volatile("cp.async.wait_group 0;" ::: "memory")
#define CP_WAIT1()  asm volatile("cp.async.wait_group 1;" ::: "memory")

// mma.sync m16n8k16 bf16 -> fp32 accumulate
__device__ __forceinline__ void mma_bf16(float* d, const uint32_t* a,
                                         uint32_t b0, uint32_t b1) {
    asm volatile(
        "mma.sync.aligned.m16n8k16.row.col.f32.bf16.bf16.f32 "
        "{%0,%1,%2,%3}, {%4,%5,%6,%7}, {%8,%9}, {%0,%1,%2,%3};"
        : "+f"(d[0]), "+f"(d[1]), "+f"(d[2]), "+f"(d[3])
        : "r"(a[0]), "r"(a[1]), "r"(a[2]), "r"(a[3]), "r"(b0), "r"(b1));
}

// SMEM stage layout: 4 arrays of 128 rows x 80B pitch (64B = 32 bf16 data)
#define ROWB 80
#define ARR_BYTES (128 * ROWB)         // 10240
#define OFF_AH 0
#define OFF_AL ARR_BYTES
#define OFF_BH (2 * ARR_BYTES)
#define OFF_BL (3 * ARR_BYTES)
#define STG_BYTES (4 * ARR_BYTES)      // 40960
#define NSTAGE 3
#define SMEM_TOTAL (NSTAGE * STG_BYTES)  // 122880

__device__ __forceinline__ void load_arr(const __nv_bfloat16* __restrict__ G,
                                         int ldg, int kt, uint32_t dst, int tid) {
#pragma unroll
    for (int i = 0; i < 2; i++) {
        int idx = tid + i * 256;
        int row = idx >> 2;
        int c = idx & 3;
        cp16(dst + row * ROWB + c * 16, (const void*)(G + (size_t)row * ldg + kt + c * 8));
    }
}

// ---------------------------------------------------------------------------
// Split-bf16 HMMA GEMM.  D[M,N] = sum_k A[m,k]*B[n,k] (both K-major, NT).
// CTA tile 128x128, K-tile 32, 8 warps (4 x 2), warp tile 32x64.
// 3 products per k-step: Ah*Bh + Ah*Bl + Al*Bh  (fp32 accum).
// EPI: 0 = f32 out; 1 = +bias, split hi/lo; 2 = +bias, split hi/lo transposed.
// ---------------------------------------------------------------------------
template <int EPI>
__global__ void __launch_bounds__(256)
hmma_gemm(const __nv_bfloat16* __restrict__ Ah, const __nv_bfloat16* __restrict__ Al,
          const __nv_bfloat16* __restrict__ Bh, const __nv_bfloat16* __restrict__ Bl,
          const float* __restrict__ bias,
          float* __restrict__ Cf,
          __nv_bfloat16* __restrict__ Ch, __nv_bfloat16* __restrict__ Cl,
          int K, int lda, int ldb, int ldc,
          size_t sA, size_t sB, size_t sC)
{
    extern __shared__ char smem[];
    const uint32_t sbase = smem_u32(smem);
    const int tid = threadIdx.x;
    const int wid = tid >> 5, lane = tid & 31;
    const int wm = wid & 3;        // warp row  (4) -> 32 rows each
    const int wn = wid >> 2;       // warp col  (2) -> 64 cols each
    const int mBase = blockIdx.y * 128;
    const int nBase = blockIdx.x * 128;
    const int z = blockIdx.z;

    const __nv_bfloat16* Ahb = Ah + z * sA + (size_t)mBase * lda;
    const __nv_bfloat16* Alb = Al + z * sA + (size_t)mBase * lda;
    const __nv_bfloat16* Bhb = Bh + z * sB + (size_t)nBase * ldb;
    const __nv_bfloat16* Blb = Bl + z * sB + (size_t)nBase * ldb;

    float d[2][8][4];
#pragma unroll
    for (int i = 0; i < 2; i++)
#pragma unroll
        for (int j = 0; j < 8; j++)
#pragma unroll
            for (int e = 0; e < 4; e++) d[i][j][e] = 0.f;

    const int T = K / 32;

    // preload stages 0,1
    {
        uint32_t b0 = sbase;
        load_arr(Ahb, lda, 0, b0 + OFF_AH, tid);
        load_arr(Alb, lda, 0, b0 + OFF_AL, tid);
        load_arr(Bhb, ldb, 0, b0 + OFF_BH, tid);
        load_arr(Blb, ldb, 0, b0 + OFF_BL, tid);
        CP_COMMIT();
        uint32_t b1 = sbase + STG_BYTES;
        load_arr(Ahb, lda, 32, b1 + OFF_AH, tid);
        load_arr(Alb, lda, 32, b1 + OFF_AL, tid);
        load_arr(Bhb, ldb, 32, b1 + OFF_BH, tid);
        load_arr(Blb, ldb, 32, b1 + OFF_BL, tid);
        CP_COMMIT();
    }

    int stg = 0;
    for (int t = 0; t < T; t++) {
        if (t == T - 1) { CP_WAIT0(); } else { CP_WAIT1(); }
        __syncthreads();

        // prefetch stage t+2 (overwrites stage (t-1)%3 — all warps are past it)
        if (t + 2 < T) {
            int ps = stg + 2; if (ps >= NSTAGE) ps -= NSTAGE;
            uint32_t pb = sbase + ps * STG_BYTES;
            const int kt = (t + 2) * 32;
            load_arr(Ahb, lda, kt, pb + OFF_AH, tid);
            load_arr(Alb, lda, kt, pb + OFF_AL, tid);
            load_arr(Bhb, ldb, kt, pb + OFF_BH, tid);
            load_arr(Blb, ldb, kt, pb + OFF_BL, tid);
            CP_COMMIT();
        }

        const char* sb = smem + stg * STG_BYTES;
        const char* pAh = sb + OFF_AH;
        const char* pAl = sb + OFF_AL;
        const char* pBh = sb + OFF_BH;
        const char* pBl = sb + OFF_BL;

#pragma unroll
        for (int ks = 0; ks < 2; ks++) {
            const int cb = ks * 32 + (lane & 3) * 4;  // byte col within row
            uint32_t ah[2][4], al[2][4];
            const int ar = wm * 32 + (lane >> 2);
#pragma unroll
            for (int mf = 0; mf < 2; mf++) {
                const int r = ar + mf * 16;
                ah[mf][0] = *(const uint32_t*)(pAh + r * ROWB + cb);
                ah[mf][1] = *(const uint32_t*)(pAh + (r + 8) * ROWB + cb);
                ah[mf][2] = *(const uint32_t*)(pAh + r * ROWB + cb + 16);
                ah[mf][3] = *(const uint32_t*)(pAh + (r + 8) * ROWB + cb + 16);
                al[mf][0] = *(const uint32_t*)(pAl + r * ROWB + cb);
                al[mf][1] = *(const uint32_t*)(pAl + (r + 8) * ROWB + cb);
                al[mf][2] = *(const uint32_t*)(pAl + r * ROWB + cb + 16);
                al[mf][3] = *(const uint32_t*)(pAl + (r + 8) * ROWB + cb + 16);
            }
            const int nr0 = wn * 64 + (lane >> 2);
#pragma unroll
            for (int nf = 0; nf < 8; nf++) {
                const int nr = nr0 + nf * 8;
                uint32_t bh0 = *(const uint32_t*)(pBh + nr * ROWB + cb);
                uint32_t bh1 = *(const uint32_t*)(pBh + nr * ROWB + cb + 16);
                uint32_t bl0 = *(const uint32_t*)(pBl + nr * ROWB + cb);
                uint32_t bl1 = *(const uint32_t*)(pBl + nr * ROWB + cb + 16);
#pragma unroll
                for (int mf = 0; mf < 2; mf++) {
                    mma_bf16(d[mf][nf], ah[mf], bh0, bh1);
                    mma_bf16(d[mf][nf], ah[mf], bl0, bl1);
                    mma_bf16(d[mf][nf], al[mf], bh0, bh1);
                }
            }
        }

        stg++; if (stg >= NSTAGE) stg = 0;
    }

    // ------------------------------------------------------------- epilogue
    const int row0 = mBase + wm * 32 + (lane >> 2);
    const int col0 = nBase + wn * 64 + (lane & 3) * 2;

#pragma unroll
    for (int mf = 0; mf < 2; mf++) {
#pragma unroll
        for (int nf = 0; nf < 8; nf++) {
            const int r = row0 + mf * 16;
            const int c = col0 + nf * 8;
            const float* dd = d[mf][nf];

            if (EPI == 0) {
                float* Cp = Cf + z * sC;
                *(float2*)(Cp + (size_t)r * ldc + c) = make_float2(dd[0], dd[1]);
                *(float2*)(Cp + (size_t)(r + 8) * ldc + c) = make_float2(dd[2], dd[3]);
            } else if (EPI == 1) {
                const float b0v = bias[c], b1v = bias[c + 1];
#pragma unroll
                for (int h = 0; h < 2; h++) {
                    float v0 = dd[h * 2 + 0] + b0v;
                    float v1 = dd[h * 2 + 1] + b1v;
                    __nv_bfloat16 h0 = __float2bfloat16(v0);
                    __nv_bfloat16 h1 = __float2bfloat16(v1);
                    __nv_bfloat16 l0 = __float2bfloat16(v0 - __bfloat162float(h0));
                    __nv_bfloat16 l1 = __float2bfloat16(v1 - __bfloat162float(h1));
                    size_t o = (size_t)(r + h * 8) * ldc + c;
                    *(__nv_bfloat162*)(Ch + o) = __nv_bfloat162(h0, h1);
                    *(__nv_bfloat162*)(Cl + o) = __nv_bfloat162(l0, l1);
                }
            } else {
                const float b0v = bias[c], b1v = bias[c + 1];
#pragma unroll
                for (int h = 0; h < 2; h++) {
                    float v0 = dd[h * 2 + 0] + b0v;
                    float v1 = dd[h * 2 + 1] + b1v;
                    __nv_bfloat16 h0 = __float2bfloat16(v0);
                    __nv_bfloat16 h1 = __float2bfloat16(v1);
                    __nv_bfloat16 l0 = __float2bfloat16(v0 - __bfloat162float(h0));
                    __nv_bfloat16 l1 = __float2bfloat16(v1 - __bfloat162float(h1));
                    int rr = r + h * 8;
                    Ch[(size_t)c * ldc + rr] = h0;
                    Cl[(size_t)c * ldc + rr] = l0;
                    Ch[(size_t)(c + 1) * ldc + rr] = h1;
                    Cl[(size_t)(c + 1) * ldc + rr] = l1;
                }
            }
        }
    }
}

// ---------------------------------------------------------------------------
// fp32 -> (hi, lo) bf16 split
// ---------------------------------------------------------------------------
__global__ void __launch_bounds__(256)
split_f32(const float4* __restrict__ x, __nv_bfloat16* __restrict__ hi,
          __nv_bfloat16* __restrict__ lo, int n4)
{
    int i = blockIdx.x * 256 + threadIdx.x;
    if (i >= n4) return;
    float4 v = x[i];
    float vv[4] = {v.x, v.y, v.z, v.w};
    __nv_bfloat162 h2[2], l2[2];
#pragma unroll
    for (int j = 0; j < 4; j++) {
        __nv_bfloat16 h = __float2bfloat16(vv[j]);
        __nv_bfloat16 l = __float2bfloat16(vv[j] - __bfloat162float(h));
        ((__nv_bfloat16*)h2)[j] = h;
        ((__nv_bfloat16*)l2)[j] = l;
    }
    ((__nv_bfloat162*)hi)[i * 2]     = h2[0];
    ((__nv_bfloat162*)hi)[i * 2 + 1] = h2[1];
    ((__nv_bfloat162*)lo)[i * 2]     = l2[0];
    ((__nv_bfloat162*)lo)[i * 2 + 1] = l2[1];
}

// W[K,N] fp32 -> WT hi/lo [N,K] bf16
__global__ void __launch_bounds__(256)
transpose_split(const float* __restrict__ W, __nv_bfloat16* __restrict__ Th,
                __nv_bfloat16* __restrict__ Tl, int rows, int cols)
{
    __shared__ float tile[32][33];
    int bx = blockIdx.x * 32;  // n
    int by = blockIdx.y * 32;  // k
    int tx = threadIdx.x & 31;
    int ty = threadIdx.x >> 5; // 0..7
#pragma unroll
    for (int i = ty; i < 32; i += 8)
        tile[i][tx] = W[(size_t)(by + i) * cols + bx + tx];
    __syncthreads();
#pragma unroll
    for (int i = ty; i < 32; i += 8) {
        float v = tile[tx][i];  // = W[by+tx][bx+i]
        __nv_bfloat16 h = __float2bfloat16(v);
        __nv_bfloat16 l = __float2bfloat16(v - __bfloat162float(h));
        size_t o = (size_t)(bx + i) * rows + by + tx;
        Th[o] = h;
        Tl[o] = l;
    }
}

// ---------------------------------------------------------------------------
// scale+mask+softmax, fp32 logits in -> bf16 hi/lo attn out
// ---------------------------------------------------------------------------
__global__ void __launch_bounds__(256)
softmax_split(const float* __restrict__ logits, const float* __restrict__ mask,
              __nv_bfloat16* __restrict__ ah, __nv_bfloat16* __restrict__ al,
              float scale)
{
    __shared__ float red[8];
    __shared__ float bval;

    size_t row = blockIdx.x;
    int q = (int)(row & (SDIM - 1));
    const float* rp = logits + row * (size_t)SDIM;
    const float* mp = mask + (size_t)q * SDIM;
    int t = threadIdx.x;

    float4 a = ((const float4*)rp)[t];
    float4 b = ((const float4*)rp)[t + 256];
    float4 ma = ((const float4*)mp)[t];
    float4 mb = ((const float4*)mp)[t + 256];
    float x[8];
    x[0] = fmaf(a.x, scale, ma.x); x[1] = fmaf(a.y, scale, ma.y);
    x[2] = fmaf(a.z, scale, ma.z); x[3] = fmaf(a.w, scale, ma.w);
    x[4] = fmaf(b.x, scale, mb.x); x[5] = fmaf(b.y, scale, mb.y);
    x[6] = fmaf(b.z, scale, mb.z); x[7] = fmaf(b.w, scale, mb.w);

    float mx = x[0];
#pragma unroll
    for (int i = 1; i < 8; i++) mx = fmaxf(mx, x[i]);
#pragma unroll
    for (int o = 16; o; o >>= 1) mx = fmaxf(mx, __shfl_xor_sync(0xffffffffu, mx, o));
    if ((t & 31) == 0) red[t >> 5] = mx;
    __syncthreads();
    if (t == 0) {
        float m = red[0];
#pragma unroll
        for (int i = 1; i < 8; i++) m = fmaxf(m, red[i]);
        bval = m;
    }
    __syncthreads();
    mx = bval;

    float s = 0.f;
#pragma unroll
    for (int i = 0; i < 8; i++) { x[i] = __expf(x[i] - mx); s += x[i]; }
#pragma unroll
    for (int o = 16; o; o >>= 1) s += __shfl_xor_sync(0xffffffffu, s, o);
    if ((t & 31) == 0) red[t >> 5] = s;
    __syncthreads();
    if (t == 0) {
        float ss = 0.f;
#pragma unroll
        for (int i = 0; i < 8; i++) ss += red[i];
        bval = 1.f / ss;
    }
    __syncthreads();
    float inv = bval;

    __nv_bfloat162* ah2 = (__nv_bfloat162*)(ah + row * (size_t)SDIM);
    __nv_bfloat162* al2 = (__nv_bfloat162*)(al + row * (size_t)SDIM);
#pragma unroll
    for (int half = 0; half < 2; half++) {
#pragma unroll
        for (int p = 0; p < 2; p++) {
            float p0 = x[half * 4 + p * 2 + 0] * inv;
            float p1 = x[half * 4 + p * 2 + 1] * inv;
            __nv_bfloat16 h0 = __float2bfloat16(p0);
            __nv_bfloat16 h1 = __float2bfloat16(p1);
            __nv_bfloat16 l0 = __float2bfloat16(p0 - __bfloat162float(h0));
            __nv_bfloat16 l1 = __float2bfloat16(p1 - __bfloat162float(h1));
            int idx = half * 512 + t * 2 + p;
            ah2[idx] = __nv_bfloat162(h0, h1);
            al2[idx] = __nv_bfloat162(l0, l1);
        }
    }
}

// ---------------------------------------------------------------------------
extern "C" void kernel_launch(void* const* d_in, const int* in_sizes, int n_in,
                              void* d_out, int out_size)
{
    const float* q    = (const float*)d_in[0];
    const float* k    = (const float*)d_in[1];
    const float* v    = (const float*)d_in[2];
    const float* mask = (const float*)d_in[3];
    const float* wq   = (const float*)d_in[4];
    const float* bq   = (const float*)d_in[5];
    const float* wk   = (const float*)d_in[6];
    const float* bk   = (const float*)d_in[7];
    const float* wv   = (const float*)d_in[8];
    const float* bv   = (const float*)d_in[9];
    float* out = (float*)d_out;

#define SYM(p, s) do { void* _t; cudaGetSymbolAddress(&_t, s); p = (decltype(p))_t; } while (0)
    __nv_bfloat16 *qh, *ql, *kh, *kl, *vh, *vl;
    __nv_bfloat16 *wqth, *wqtl, *wkth, *wktl, *wvth, *wvtl;
    __nv_bfloat16 *qph, *qpl, *kph, *kpl, *vpth, *vptl, *ah, *al;
    float* lg;
    SYM(qh, g_qh); SYM(ql, g_ql); SYM(kh, g_kh); SYM(kl, g_kl);
    SYM(vh, g_vh); SYM(vl, g_vl);
    SYM(wqth, g_wqt_h); SYM(wqtl, g_wqt_l);
    SYM(wkth, g_wkt_h); SYM(wktl, g_wkt_l);
    SYM(wvth, g_wvt_h); SYM(wvtl, g_wvt_l);
    SYM(qph, g_qph); SYM(qpl, g_qpl); SYM(kph, g_kph); SYM(kpl, g_kpl);
    SYM(vpth, g_vpth); SYM(vptl, g_vptl);
    SYM(ah, g_ah); SYM(al, g_al);
    SYM(lg, g_logits);
#undef SYM

    cudaFuncSetAttribute(hmma_gemm<0>, cudaFuncAttributeMaxDynamicSharedMemorySize, SMEM_TOTAL);
    cudaFuncSetAttribute(hmma_gemm<1>, cudaFuncAttributeMaxDynamicSharedMemorySize, SMEM_TOTAL);
    cudaFuncSetAttribute(hmma_gemm<2>, cudaFuncAttributeMaxDynamicSharedMemorySize, SMEM_TOTAL);

    // 1. split inputs to bf16 hi/lo
    const int n4 = NTOK * IDIM / 4;
    split_f32<<<n4 / 256, 256>>>((const float4*)q, qh, ql, n4);
    split_f32<<<n4 / 256, 256>>>((const float4*)k, kh, kl, n4);
    split_f32<<<n4 / 256, 256>>>((const float4*)v, vh, vl, n4);

    // 2. transpose + split weights: W[K,N] -> WT[N,K]
    dim3 tg(IDIM / 32, IDIM / 32);
    transpose_split<<<tg, 256>>>(wq, wqth, wqtl, IDIM, DDIM);
    transpose_split<<<tg, 256>>>(wk, wkth, wktl, IDIM, DDIM);
    transpose_split<<<tg, 256>>>(wv, wvth, wvtl, IDIM, DDIM);

    // 3. projections: [8192,1024] = q @ Wq  (NT with WT)
    dim3 gp(DDIM / 128, NTOK / 128, 1);
    hmma_gemm<1><<<gp, 256, SMEM_TOTAL>>>(qh, ql, wqth, wqtl, bq,
                                          nullptr, qph, qpl,
                                          IDIM, IDIM, IDIM, DDIM, 0, 0, 0);
    hmma_gemm<1><<<gp, 256, SMEM_TOTAL>>>(kh, kl, wkth, wktl, bk,
                                          nullptr, kph, kpl,
                                          IDIM, IDIM, IDIM, DDIM, 0, 0, 0);
    // V projection writes vp^T [D, tokens] directly
    hmma_gemm<2><<<gp, 256, SMEM_TOTAL>>>(vh, vl, wvth, wvtl, bv,
                                          nullptr, vpth, vptl,
                                          IDIM, IDIM, IDIM, NTOK, 0, 0, 0);

    // 4. logits = qp @ kp^T  (batched)
    dim3 gl(SDIM / 128, SDIM / 128, BDIM);
    hmma_gemm<0><<<gl, 256, SMEM_TOTAL>>>(qph, qpl, kph, kpl, nullptr,
                                          lg, nullptr, nullptr,
                                          DDIM, DDIM, DDIM, SDIM,
                                          (size_t)SDIM * DDIM, (size_t)SDIM * DDIM,
                                          (size_t)SDIM * SDIM);

    // 5. softmax -> attn hi/lo
    softmax_split<<<BDIM * SDIM, 256>>>(lg, mask, ah, al, 0.03125f);

    // 6. out = attn @ vp  (B operand = vp^T, K-major; batch offset = column shift)
    dim3 ga(DDIM / 128, SDIM / 128, BDIM);
    hmma_gemm<0><<<ga, 256, SMEM_TOTAL>>>(ah, al, vpth, vptl, nullptr,
                                          out, nullptr, nullptr,
                                          SDIM, SDIM, NTOK, DDIM,
                                          (size_t)SDIM * SDIM, (size_t)SDIM,
                                          (size_t)SDIM * DDIM);
}

// round 4
// speedup vs baseline: 2.2775x; 1.0697x over previous
#include <cuda_runtime.h>
#include <cuda_bf16.h>
#include <cstdint>

#define BDIM 4
#define SDIM 2048
#define IDIM 1024
#define DDIM 1024
#define NTOK (BDIM * SDIM)   // 8192

// ---------------------------------------------------------------------------
// Device scratch (allocation-free rule)
// ---------------------------------------------------------------------------
__device__ __align__(128) __nv_bfloat16 g_qh[(size_t)NTOK * IDIM];
__device__ __align__(128) __nv_bfloat16 g_ql[(size_t)NTOK * IDIM];
__device__ __align__(128) __nv_bfloat16 g_kh[(size_t)NTOK * IDIM];
__device__ __align__(128) __nv_bfloat16 g_kl[(size_t)NTOK * IDIM];
__device__ __align__(128) __nv_bfloat16 g_vh[(size_t)NTOK * IDIM];
__device__ __align__(128) __nv_bfloat16 g_vl[(size_t)NTOK * IDIM];
__device__ __align__(128) __nv_bfloat16 g_wqt_h[(size_t)DDIM * IDIM];
__device__ __align__(128) __nv_bfloat16 g_wqt_l[(size_t)DDIM * IDIM];
__device__ __align__(128) __nv_bfloat16 g_wkt_h[(size_t)DDIM * IDIM];
__device__ __align__(128) __nv_bfloat16 g_wkt_l[(size_t)DDIM * IDIM];
__device__ __align__(128) __nv_bfloat16 g_wvt_h[(size_t)DDIM * IDIM];
__device__ __align__(128) __nv_bfloat16 g_wvt_l[(size_t)DDIM * IDIM];
__device__ __align__(128) __nv_bfloat16 g_qph[(size_t)NTOK * DDIM];
__device__ __align__(128) __nv_bfloat16 g_qpl[(size_t)NTOK * DDIM];
__device__ __align__(128) __nv_bfloat16 g_kph[(size_t)NTOK * DDIM];
__device__ __align__(128) __nv_bfloat16 g_kpl[(size_t)NTOK * DDIM];
__device__ __align__(128) __nv_bfloat16 g_vpth[(size_t)DDIM * NTOK];  // [D, tokens]
__device__ __align__(128) __nv_bfloat16 g_vptl[(size_t)DDIM * NTOK];
__device__ __align__(128) float g_logits[(size_t)BDIM * SDIM * SDIM];
__device__ __align__(128) __nv_bfloat16 g_ah[(size_t)BDIM * SDIM * SDIM];
__device__ __align__(128) __nv_bfloat16 g_al[(size_t)BDIM * SDIM * SDIM];

// ---------------------------------------------------------------------------
// PTX helpers (no tcgen05 — harness compiles for compute_103 w/o 'a' features)
// ---------------------------------------------------------------------------
__device__ __forceinline__ uint32_t smem_u32(const void* p) {
    uint32_t a;
    asm("{ .reg .u64 t; cvta.to.shared.u64 t, %1; cvt.u32.u64 %0, t; }"
        : "=r"(a) : "l"(p));
    return a;
}

__device__ __forceinline__ void cp16(uint32_t d, const void* g) {
    asm volatile("cp.async.cg.shared.global [%0], [%1], 16;" :: "r"(d), "l"(g) : "memory");
}
#define CP_COMMIT() asm volatile("cp.async.commit_group;" ::: "memory")
#define CP_WAIT2()  asm volatile("cp.async.wait_group 2;" ::: "memory")

__device__ __forceinline__ void ldsm4(uint32_t* r, uint32_t addr) {
    asm volatile("ldmatrix.sync.aligned.m8n8.x4.shared.b16 {%0,%1,%2,%3}, [%4];"
        : "=r"(r[0]), "=r"(r[1]), "=r"(r[2]), "=r"(r[3]) : "r"(addr));
}

// mma.sync m16n8k16 bf16 -> fp32 accumulate
__device__ __forceinline__ void mma_bf16(float* d, const uint32_t* a,
                                         uint32_t b0, uint32_t b1) {
    asm volatile(
        "mma.sync.aligned.m16n8k16.row.col.f32.bf16.bf16.f32 "
        "{%0,%1,%2,%3}, {%4,%5,%6,%7}, {%8,%9}, {%0,%1,%2,%3};"
        : "+f"(d[0]), "+f"(d[1]), "+f"(d[2]), "+f"(d[3])
        : "r"(a[0]), "r"(a[1]), "r"(a[2]), "r"(a[3]), "r"(b0), "r"(b1));
}

// SMEM stage layout: 4 arrays of 128 rows x 80B pitch (64B = 32 bf16 data)
#define ROWB 80
#define ARR_BYTES (128 * ROWB)         // 10240
#define OFF_AH 0
#define OFF_AL ARR_BYTES
#define OFF_BH (2 * ARR_BYTES)
#define OFF_BL (3 * ARR_BYTES)
#define STG_BYTES (4 * ARR_BYTES)      // 40960
#define NSTAGE 4
#define SMEM_TOTAL (NSTAGE * STG_BYTES)  // 163840

__device__ __forceinline__ void load_arr(const __nv_bfloat16* __restrict__ G,
                                         int ldg, int kt, uint32_t dst, int tid) {
#pragma unroll
    for (int i = 0; i < 2; i++) {
        int idx = tid + i * 256;
        int row = idx >> 2;
        int c = idx & 3;
        cp16(dst + row * ROWB + c * 16, (const void*)(G + (size_t)row * ldg + kt + c * 8));
    }
}

// ---------------------------------------------------------------------------
// Split-bf16 HMMA GEMM.  D[M,N] = sum_k A[m,k]*B[n,k] (both K-major, NT).
// CTA tile 128x128, K-tile 32, 8 warps (4 x 2), warp tile 32x64.
// 3 products per k-step: Ah*Bh + Ah*Bl + Al*Bh  (fp32 accum).
// ldmatrix fragment loads; 4-stage cp.async pipeline.
// EPI: 0 = f32 out; 1 = +bias, split hi/lo; 2 = +bias, split hi/lo transposed.
// ---------------------------------------------------------------------------
template <int EPI>
__global__ void __launch_bounds__(256)
hmma_gemm(const __nv_bfloat16* __restrict__ Ah, const __nv_bfloat16* __restrict__ Al,
          const __nv_bfloat16* __restrict__ Bh, const __nv_bfloat16* __restrict__ Bl,
          const float* __restrict__ bias,
          float* __restrict__ Cf,
          __nv_bfloat16* __restrict__ Ch, __nv_bfloat16* __restrict__ Cl,
          int K, int lda, int ldb, int ldc,
          size_t sA, size_t sB, size_t sC)
{
    extern __shared__ char smem[];
    const uint32_t sbase = smem_u32(smem);
    const int tid = threadIdx.x;
    const int wid = tid >> 5, lane = tid & 31;
    const int wm = wid & 3;        // warp row  (4) -> 32 rows each
    const int wn = wid >> 2;       // warp col  (2) -> 64 cols each
    const int mBase = blockIdx.y * 128;
    const int nBase = blockIdx.x * 128;
    const int z = blockIdx.z;

    const __nv_bfloat16* Ahb = Ah + z * sA + (size_t)mBase * lda;
    const __nv_bfloat16* Alb = Al + z * sA + (size_t)mBase * lda;
    const __nv_bfloat16* Bhb = Bh + z * sB + (size_t)nBase * ldb;
    const __nv_bfloat16* Blb = Bl + z * sB + (size_t)nBase * ldb;

    // ldmatrix per-lane source offsets (within one array)
    const int w8 = lane & 7, j8 = lane >> 3;
    int aoff[2], boff[4];
#pragma unroll
    for (int mf = 0; mf < 2; mf++)
        aoff[mf] = (wm * 32 + mf * 16 + w8 + 8 * (j8 & 1)) * ROWB + (j8 >> 1) * 16;
#pragma unroll
    for (int g = 0; g < 4; g++)
        boff[g] = (wn * 64 + g * 16 + w8 + 8 * (j8 >> 1)) * ROWB + (j8 & 1) * 16;

    float d[2][8][4];
#pragma unroll
    for (int i = 0; i < 2; i++)
#pragma unroll
        for (int j = 0; j < 8; j++)
#pragma unroll
            for (int e = 0; e < 4; e++) d[i][j][e] = 0.f;

    const int T = K / 32;

    // preload stages 0..2
#pragma unroll
    for (int p = 0; p < 3; p++) {
        uint32_t b = sbase + p * STG_BYTES;
        load_arr(Ahb, lda, p * 32, b + OFF_AH, tid);
        load_arr(Alb, lda, p * 32, b + OFF_AL, tid);
        load_arr(Bhb, ldb, p * 32, b + OFF_BH, tid);
        load_arr(Blb, ldb, p * 32, b + OFF_BL, tid);
        CP_COMMIT();
    }

    int stg = 0;
    for (int t = 0; t < T; t++) {
        CP_WAIT2();          // stage t complete (always exactly 3 groups pending)
        __syncthreads();

        // prefetch stage t+3 into slot (stg+3)%4 (empty commit keeps count fixed)
        if (t + 3 < T) {
            int ps = stg + 3; if (ps >= NSTAGE) ps -= NSTAGE;
            uint32_t pb = sbase + ps * STG_BYTES;
            const int kt = (t + 3) * 32;
            load_arr(Ahb, lda, kt, pb + OFF_AH, tid);
            load_arr(Alb, lda, kt, pb + OFF_AL, tid);
            load_arr(Bhb, ldb, kt, pb + OFF_BH, tid);
            load_arr(Blb, ldb, kt, pb + OFF_BL, tid);
        }
        CP_COMMIT();

        const uint32_t sb = sbase + stg * STG_BYTES;
        const uint32_t sAh = sb + OFF_AH;
        const uint32_t sAl = sb + OFF_AL;
        const uint32_t sBh = sb + OFF_BH;
        const uint32_t sBl = sb + OFF_BL;

#pragma unroll
        for (int ks = 0; ks < 2; ks++) {
            const int kb = ks * 32;
            uint32_t ah[2][4], al[2][4];
            ldsm4(ah[0], sAh + aoff[0] + kb);
            ldsm4(ah[1], sAh + aoff[1] + kb);
            ldsm4(al[0], sAl + aoff[0] + kb);
            ldsm4(al[1], sAl + aoff[1] + kb);
#pragma unroll
            for (int g = 0; g < 4; g++) {
                uint32_t bh[4], bl[4];
                ldsm4(bh, sBh + boff[g] + kb);
                ldsm4(bl, sBl + boff[g] + kb);
#pragma unroll
                for (int sub = 0; sub < 2; sub++) {
                    const int nf = g * 2 + sub;
                    const uint32_t bh0 = bh[sub * 2], bh1 = bh[sub * 2 + 1];
                    const uint32_t bl0 = bl[sub * 2], bl1 = bl[sub * 2 + 1];
#pragma unroll
                    for (int mf = 0; mf < 2; mf++) {
                        mma_bf16(d[mf][nf], ah[mf], bh0, bh1);
                        mma_bf16(d[mf][nf], ah[mf], bl0, bl1);
                        mma_bf16(d[mf][nf], al[mf], bh0, bh1);
                    }
                }
            }
        }

        stg++; if (stg >= NSTAGE) stg = 0;
    }

    // ------------------------------------------------------------- epilogue
    const int row0 = mBase + wm * 32 + (lane >> 2);
    const int col0 = nBase + wn * 64 + (lane & 3) * 2;

#pragma unroll
    for (int mf = 0; mf < 2; mf++) {
#pragma unroll
        for (int nf = 0; nf < 8; nf++) {
            const int r = row0 + mf * 16;
            const int c = col0 + nf * 8;
            const float* dd = d[mf][nf];

            if (EPI == 0) {
                float* Cp = Cf + z * sC;
                *(float2*)(Cp + (size_t)r * ldc + c) = make_float2(dd[0], dd[1]);
                *(float2*)(Cp + (size_t)(r + 8) * ldc + c) = make_float2(dd[2], dd[3]);
            } else if (EPI == 1) {
                const float b0v = bias[c], b1v = bias[c + 1];
#pragma unroll
                for (int h = 0; h < 2; h++) {
                    float v0 = dd[h * 2 + 0] + b0v;
                    float v1 = dd[h * 2 + 1] + b1v;
                    __nv_bfloat16 h0 = __float2bfloat16(v0);
                    __nv_bfloat16 h1 = __float2bfloat16(v1);
                    __nv_bfloat16 l0 = __float2bfloat16(v0 - __bfloat162float(h0));
                    __nv_bfloat16 l1 = __float2bfloat16(v1 - __bfloat162float(h1));
                    size_t o = (size_t)(r + h * 8) * ldc + c;
                    *(__nv_bfloat162*)(Ch + o) = __nv_bfloat162(h0, h1);
                    *(__nv_bfloat162*)(Cl + o) = __nv_bfloat162(l0, l1);
                }
            } else {
                const float b0v = bias[c], b1v = bias[c + 1];
#pragma unroll
                for (int h = 0; h < 2; h++) {
                    float v0 = dd[h * 2 + 0] + b0v;
                    float v1 = dd[h * 2 + 1] + b1v;
                    __nv_bfloat16 h0 = __float2bfloat16(v0);
                    __nv_bfloat16 h1 = __float2bfloat16(v1);
                    __nv_bfloat16 l0 = __float2bfloat16(v0 - __bfloat162float(h0));
                    __nv_bfloat16 l1 = __float2bfloat16(v1 - __bfloat162float(h1));
                    int rr = r + h * 8;
                    Ch[(size_t)c * ldc + rr] = h0;
                    Cl[(size_t)c * ldc + rr] = l0;
                    Ch[(size_t)(c + 1) * ldc + rr] = h1;
                    Cl[(size_t)(c + 1) * ldc + rr] = l1;
                }
            }
        }
    }
}

// ---------------------------------------------------------------------------
// fp32 -> (hi, lo) bf16 split
// ---------------------------------------------------------------------------
__global__ void __launch_bounds__(256)
split_f32(const float4* __restrict__ x, __nv_bfloat16* __restrict__ hi,
          __nv_bfloat16* __restrict__ lo, int n4)
{
    int i = blockIdx.x * 256 + threadIdx.x;
    if (i >= n4) return;
    float4 v = x[i];
    float vv[4] = {v.x, v.y, v.z, v.w};
    __nv_bfloat162 h2[2], l2[2];
#pragma unroll
    for (int j = 0; j < 4; j++) {
        __nv_bfloat16 h = __float2bfloat16(vv[j]);
        __nv_bfloat16 l = __float2bfloat16(vv[j] - __bfloat162float(h));
        ((__nv_bfloat16*)h2)[j] = h;
        ((__nv_bfloat16*)l2)[j] = l;
    }
    ((__nv_bfloat162*)hi)[i * 2]     = h2[0];
    ((__nv_bfloat162*)hi)[i * 2 + 1] = h2[1];
    ((__nv_bfloat162*)lo)[i * 2]     = l2[0];
    ((__nv_bfloat162*)lo)[i * 2 + 1] = l2[1];
}

// W[K,N] fp32 -> WT hi/lo [N,K] bf16
__global__ void __launch_bounds__(256)
transpose_split(const float* __restrict__ W, __nv_bfloat16* __restrict__ Th,
                __nv_bfloat16* __restrict__ Tl, int rows, int cols)
{
    __shared__ float tile[32][33];
    int bx = blockIdx.x * 32;  // n
    int by = blockIdx.y * 32;  // k
    int tx = threadIdx.x & 31;
    int ty = threadIdx.x >> 5; // 0..7
#pragma unroll
    for (int i = ty; i < 32; i += 8)
        tile[i][tx] = W[(size_t)(by + i) * cols + bx + tx];
    __syncthreads();
#pragma unroll
    for (int i = ty; i < 32; i += 8) {
        float v = tile[tx][i];  // = W[by+tx][bx+i]
        __nv_bfloat16 h = __float2bfloat16(v);
        __nv_bfloat16 l = __float2bfloat16(v - __bfloat162float(h));
        size_t o = (size_t)(bx + i) * rows + by + tx;
        Th[o] = h;
        Tl[o] = l;
    }
}

// ---------------------------------------------------------------------------
// scale+mask+softmax, fp32 logits in -> bf16 hi/lo attn out
// ---------------------------------------------------------------------------
__global__ void __launch_bounds__(256)
softmax_split(const float* __restrict__ logits, const float* __restrict__ mask,
              __nv_bfloat16* __restrict__ ah, __nv_bfloat16* __restrict__ al,
              float scale)
{
    __shared__ float red[8];
    __shared__ float bval;

    size_t row = blockIdx.x;
    int q = (int)(row & (SDIM - 1));
    const float* rp = logits + row * (size_t)SDIM;
    const float* mp = mask + (size_t)q * SDIM;
    int t = threadIdx.x;

    float4 a = ((const float4*)rp)[t];
    float4 b = ((const float4*)rp)[t + 256];
    float4 ma = ((const float4*)mp)[t];
    float4 mb = ((const float4*)mp)[t + 256];
    float x[8];
    x[0] = fmaf(a.x, scale, ma.x); x[1] = fmaf(a.y, scale, ma.y);
    x[2] = fmaf(a.z, scale, ma.z); x[3] = fmaf(a.w, scale, ma.w);
    x[4] = fmaf(b.x, scale, mb.x); x[5] = fmaf(b.y, scale, mb.y);
    x[6] = fmaf(b.z, scale, mb.z); x[7] = fmaf(b.w, scale, mb.w);

    float mx = x[0];
#pragma unroll
    for (int i = 1; i < 8; i++) mx = fmaxf(mx, x[i]);
#pragma unroll
    for (int o = 16; o; o >>= 1) mx = fmaxf(mx, __shfl_xor_sync(0xffffffffu, mx, o));
    if ((t & 31) == 0) red[t >> 5] = mx;
    __syncthreads();
    if (t == 0) {
        float m = red[0];
#pragma unroll
        for (int i = 1; i < 8; i++) m = fmaxf(m, red[i]);
        bval = m;
    }
    __syncthreads();
    mx = bval;

    float s = 0.f;
#pragma unroll
    for (int i = 0; i < 8; i++) { x[i] = __expf(x[i] - mx); s += x[i]; }
#pragma unroll
    for (int o = 16; o; o >>= 1) s += __shfl_xor_sync(0xffffffffu, s, o);
    if ((t & 31) == 0) red[t >> 5] = s;
    __syncthreads();
    if (t == 0) {
        float ss = 0.f;
#pragma unroll
        for (int i = 0; i < 8; i++) ss += red[i];
        bval = 1.f / ss;
    }
    __syncthreads();
    float inv = bval;

    __nv_bfloat162* ah2 = (__nv_bfloat162*)(ah + row * (size_t)SDIM);
    __nv_bfloat162* al2 = (__nv_bfloat162*)(al + row * (size_t)SDIM);
#pragma unroll
    for (int half = 0; half < 2; half++) {
#pragma unroll
        for (int p = 0; p < 2; p++) {
            float p0 = x[half * 4 + p * 2 + 0] * inv;
            float p1 = x[half * 4 + p * 2 + 1] * inv;
            __nv_bfloat16 h0 = __float2bfloat16(p0);
            __nv_bfloat16 h1 = __float2bfloat16(p1);
            __nv_bfloat16 l0 = __float2bfloat16(p0 - __bfloat162float(h0));
            __nv_bfloat16 l1 = __float2bfloat16(p1 - __bfloat162float(h1));
            int idx = half * 512 + t * 2 + p;
            ah2[idx] = __nv_bfloat162(h0, h1);
            al2[idx] = __nv_bfloat162(l0, l1);
        }
    }
}

// ---------------------------------------------------------------------------
extern "C" void kernel_launch(void* const* d_in, const int* in_sizes, int n_in,
                              void* d_out, int out_size)
{
    const float* q    = (const float*)d_in[0];
    const float* k    = (const float*)d_in[1];
    const float* v    = (const float*)d_in[2];
    const float* mask = (const float*)d_in[3];
    const float* wq   = (const float*)d_in[4];
    const float* bq   = (const float*)d_in[5];
    const float* wk   = (const float*)d_in[6];
    const float* bk   = (const float*)d_in[7];
    const float* wv   = (const float*)d_in[8];
    const float* bv   = (const float*)d_in[9];
    float* out = (float*)d_out;

#define SYM(p, s) do { void* _t; cudaGetSymbolAddress(&_t, s); p = (decltype(p))_t; } while (0)
    __nv_bfloat16 *qh, *ql, *kh, *kl, *vh, *vl;
    __nv_bfloat16 *wqth, *wqtl, *wkth, *wktl, *wvth, *wvtl;
    __nv_bfloat16 *qph, *qpl, *kph, *kpl, *vpth, *vptl, *ah, *al;
    float* lg;
    SYM(qh, g_qh); SYM(ql, g_ql); SYM(kh, g_kh); SYM(kl, g_kl);
    SYM(vh, g_vh); SYM(vl, g_vl);
    SYM(wqth, g_wqt_h); SYM(wqtl, g_wqt_l);
    SYM(wkth, g_wkt_h); SYM(wktl, g_wkt_l);
    SYM(wvth, g_wvt_h); SYM(wvtl, g_wvt_l);
    SYM(qph, g_qph); SYM(qpl, g_qpl); SYM(kph, g_kph); SYM(kpl, g_kpl);
    SYM(vpth, g_vpth); SYM(vptl, g_vptl);
    SYM(ah, g_ah); SYM(al, g_al);
    SYM(lg, g_logits);
#undef SYM

    cudaFuncSetAttribute(hmma_gemm<0>, cudaFuncAttributeMaxDynamicSharedMemorySize, SMEM_TOTAL);
    cudaFuncSetAttribute(hmma_gemm<1>, cudaFuncAttributeMaxDynamicSharedMemorySize, SMEM_TOTAL);
    cudaFuncSetAttribute(hmma_gemm<2>, cudaFuncAttributeMaxDynamicSharedMemorySize, SMEM_TOTAL);

    const int n4 = NTOK * IDIM / 4;
    dim3 tg(IDIM / 32, IDIM / 32);
    dim3 gp(DDIM / 128, NTOK / 128, 1);

    // Launch order arranged so launch #6 (ncu -s 5 -c 1) is the Q-proj GEMM.
    split_f32<<<n4 / 256, 256>>>((const float4*)q, qh, ql, n4);            // 1
    split_f32<<<n4 / 256, 256>>>((const float4*)k, kh, kl, n4);            // 2
    split_f32<<<n4 / 256, 256>>>((const float4*)v, vh, vl, n4);            // 3
    transpose_split<<<tg, 256>>>(wq, wqth, wqtl, IDIM, DDIM);              // 4
    transpose_split<<<tg, 256>>>(wk, wkth, wktl, IDIM, DDIM);              // 5
    hmma_gemm<1><<<gp, 256, SMEM_TOTAL>>>(qh, ql, wqth, wqtl, bq,          // 6 <- ncu
                                          nullptr, qph, qpl,
                                          IDIM, IDIM, IDIM, DDIM, 0, 0, 0);
    hmma_gemm<1><<<gp, 256, SMEM_TOTAL>>>(kh, kl, wkth, wktl, bk,          // 7
                                          nullptr, kph, kpl,
                                          IDIM, IDIM, IDIM, DDIM, 0, 0, 0);
    transpose_split<<<tg, 256>>>(wv, wvth, wvtl, IDIM, DDIM);              // 8
    hmma_gemm<2><<<gp, 256, SMEM_TOTAL>>>(vh, vl, wvth, wvtl, bv,          // 9
                                          nullptr, vpth, vptl,
                                          IDIM, IDIM, IDIM, NTOK, 0, 0, 0);

    dim3 gl(SDIM / 128, SDIM / 128, BDIM);
    hmma_gemm<0><<<gl, 256, SMEM_TOTAL>>>(qph, qpl, kph, kpl, nullptr,     // 10
                                          lg, nullptr, nullptr,
                                          DDIM, DDIM, DDIM, SDIM,
                                          (size_t)SDIM * DDIM, (size_t)SDIM * DDIM,
                                          (size_t)SDIM * SDIM);

    softmax_split<<<BDIM * SDIM, 256>>>(lg, mask, ah, al, 0.03125f);       // 11

    dim3 ga(DDIM / 128, SDIM / 128, BDIM);
    hmma_gemm<0><<<ga, 256, SMEM_TOTAL>>>(ah, al, vpth, vptl, nullptr,     // 12
                                          out, nullptr, nullptr,
                                          SDIM, SDIM, NTOK, DDIM,
                                          (size_t)SDIM * SDIM, (size_t)SDIM,
                                          (size_t)SDIM * DDIM);
}

// round 5
// speedup vs baseline: 2.6072x; 1.1447x over previous
#include <cuda_runtime.h>
#include <cuda_bf16.h>
#include <cstdint>

#define BDIM 4
#define SDIM 2048
#define IDIM 1024
#define DDIM 1024
#define NTOK (BDIM * SDIM)   // 8192

// ---------------------------------------------------------------------------
// Device scratch (allocation-free rule)
// ---------------------------------------------------------------------------
__device__ __align__(128) __nv_bfloat16 g_qh[(size_t)NTOK * IDIM];
__device__ __align__(128) __nv_bfloat16 g_ql[(size_t)NTOK * IDIM];
__device__ __align__(128) __nv_bfloat16 g_kh[(size_t)NTOK * IDIM];
__device__ __align__(128) __nv_bfloat16 g_kl[(size_t)NTOK * IDIM];
__device__ __align__(128) __nv_bfloat16 g_vh[(size_t)NTOK * IDIM];
__device__ __align__(128) __nv_bfloat16 g_vl[(size_t)NTOK * IDIM];
__device__ __align__(128) __nv_bfloat16 g_wqt_h[(size_t)DDIM * IDIM];
__device__ __align__(128) __nv_bfloat16 g_wqt_l[(size_t)DDIM * IDIM];
__device__ __align__(128) __nv_bfloat16 g_wkt_h[(size_t)DDIM * IDIM];
__device__ __align__(128) __nv_bfloat16 g_wkt_l[(size_t)DDIM * IDIM];
__device__ __align__(128) __nv_bfloat16 g_wvt_h[(size_t)DDIM * IDIM];
__device__ __align__(128) __nv_bfloat16 g_wvt_l[(size_t)DDIM * IDIM];
__device__ __align__(128) __nv_bfloat16 g_qph[(size_t)NTOK * DDIM];
__device__ __align__(128) __nv_bfloat16 g_qpl[(size_t)NTOK * DDIM];
__device__ __align__(128) __nv_bfloat16 g_kph[(size_t)NTOK * DDIM];
__device__ __align__(128) __nv_bfloat16 g_kpl[(size_t)NTOK * DDIM];
__device__ __align__(128) __nv_bfloat16 g_vpth[(size_t)DDIM * NTOK];  // [D, tokens]
__device__ __align__(128) __nv_bfloat16 g_vptl[(size_t)DDIM * NTOK];
__device__ __align__(128) float g_logits[(size_t)BDIM * SDIM * SDIM];
__device__ __align__(128) __nv_bfloat16 g_ah[(size_t)BDIM * SDIM * SDIM];
__device__ __align__(128) __nv_bfloat16 g_al[(size_t)BDIM * SDIM * SDIM];

// ---------------------------------------------------------------------------
// PTX helpers (no tcgen05 — harness compiles for compute_103 w/o 'a' features)
// ---------------------------------------------------------------------------
__device__ __forceinline__ uint32_t smem_u32(const void* p) {
    uint32_t a;
    asm("{ .reg .u64 t; cvta.to.shared.u64 t, %1; cvt.u32.u64 %0, t; }"
        : "=r"(a) : "l"(p));
    return a;
}

__device__ __forceinline__ void cp16(uint32_t d, const void* g) {
    asm volatile("cp.async.cg.shared.global [%0], [%1], 16;" :: "r"(d), "l"(g) : "memory");
}
#define CP_COMMIT() asm volatile("cp.async.commit_group;" ::: "memory")
#define CP_WAIT1()  asm volatile("cp.async.wait_group 1;" ::: "memory")

__device__ __forceinline__ void ldsm4(uint32_t* r, uint32_t addr) {
    asm volatile("ldmatrix.sync.aligned.m8n8.x4.shared.b16 {%0,%1,%2,%3}, [%4];"
        : "=r"(r[0]), "=r"(r[1]), "=r"(r[2]), "=r"(r[3]) : "r"(addr));
}

// mma.sync m16n8k16 bf16 -> fp32 accumulate
__device__ __forceinline__ void mma_bf16(float* d, const uint32_t* a,
                                         uint32_t b0, uint32_t b1) {
    asm volatile(
        "mma.sync.aligned.m16n8k16.row.col.f32.bf16.bf16.f32 "
        "{%0,%1,%2,%3}, {%4,%5,%6,%7}, {%8,%9}, {%0,%1,%2,%3};"
        : "+f"(d[0]), "+f"(d[1]), "+f"(d[2]), "+f"(d[3])
        : "r"(a[0]), "r"(a[1]), "r"(a[2]), "r"(a[3]), "r"(b0), "r"(b1));
}

// SMEM stage: 4 arrays of 128 rows x 144B pitch (128B = 64 bf16 data, K-tile 64)
#define KT 64
#define ROWB 144
#define ARR_BYTES (128 * ROWB)          // 18432
#define OFF_AH 0
#define OFF_AL ARR_BYTES
#define OFF_BH (2 * ARR_BYTES)
#define OFF_BL (3 * ARR_BYTES)
#define STG_BYTES (4 * ARR_BYTES)       // 73728
#define NSTAGE 3
#define SMEM_TOTAL (NSTAGE * STG_BYTES) // 221184

__device__ __forceinline__ void load_arr(const __nv_bfloat16* __restrict__ G,
                                         int ldg, int kt, uint32_t dst, int tid) {
#pragma unroll
    for (int i = 0; i < 4; i++) {
        int idx = tid + i * 256;
        int row = idx >> 3;
        int c = idx & 7;
        cp16(dst + row * ROWB + c * 16, (const void*)(G + (size_t)row * ldg + kt + c * 8));
    }
}

// ---------------------------------------------------------------------------
// Shared mainloop: D[128,128] += A[128,K] * B[128,K]^T (NT, hi/lo 3-product).
// 8 warps (4 m-rows x 2 n-cols), warp tile 32x64.
// ---------------------------------------------------------------------------
__device__ __forceinline__ void gemm_mainloop(
    const __nv_bfloat16* __restrict__ Ahb, const __nv_bfloat16* __restrict__ Alb,
    const __nv_bfloat16* __restrict__ Bhb, const __nv_bfloat16* __restrict__ Blb,
    int K, int lda, int ldb,
    uint32_t sbase, int tid, int wm, int wn, int lane,
    float d[2][8][4])
{
    const int w8 = lane & 7, j8 = lane >> 3;
    int aoff[2], boff[4];
#pragma unroll
    for (int mf = 0; mf < 2; mf++)
        aoff[mf] = (wm * 32 + mf * 16 + w8 + 8 * (j8 & 1)) * ROWB + (j8 >> 1) * 16;
#pragma unroll
    for (int g = 0; g < 4; g++)
        boff[g] = (wn * 64 + g * 16 + w8 + 8 * (j8 >> 1)) * ROWB + (j8 & 1) * 16;

    const int T = K / KT;

    // preload stages 0,1
#pragma unroll
    for (int p = 0; p < 2; p++) {
        uint32_t b = sbase + p * STG_BYTES;
        load_arr(Ahb, lda, p * KT, b + OFF_AH, tid);
        load_arr(Alb, lda, p * KT, b + OFF_AL, tid);
        load_arr(Bhb, ldb, p * KT, b + OFF_BH, tid);
        load_arr(Blb, ldb, p * KT, b + OFF_BL, tid);
        CP_COMMIT();
    }

    int stg = 0;
    for (int t = 0; t < T; t++) {
        CP_WAIT1();            // stage t complete
        __syncthreads();

        // prefetch stage t+2 into slot (stg+2)%3 (consumed at t-1; barrier protects)
        if (t + 2 < T) {
            int ps = stg + 2; if (ps >= NSTAGE) ps -= NSTAGE;
            uint32_t pb = sbase + ps * STG_BYTES;
            const int kt = (t + 2) * KT;
            load_arr(Ahb, lda, kt, pb + OFF_AH, tid);
            load_arr(Alb, lda, kt, pb + OFF_AL, tid);
            load_arr(Bhb, ldb, kt, pb + OFF_BH, tid);
            load_arr(Blb, ldb, kt, pb + OFF_BL, tid);
        }
        CP_COMMIT();

        const uint32_t sb = sbase + stg * STG_BYTES;
        const uint32_t sAh = sb + OFF_AH;
        const uint32_t sAl = sb + OFF_AL;
        const uint32_t sBh = sb + OFF_BH;
        const uint32_t sBl = sb + OFF_BL;

#pragma unroll
        for (int ks = 0; ks < 4; ks++) {
            const int kb = ks * 32;   // 16 bf16 = 32 bytes per k-step
            uint32_t ah[2][4], al[2][4];
            ldsm4(ah[0], sAh + aoff[0] + kb);
            ldsm4(ah[1], sAh + aoff[1] + kb);
            ldsm4(al[0], sAl + aoff[0] + kb);
            ldsm4(al[1], sAl + aoff[1] + kb);
#pragma unroll
            for (int g = 0; g < 4; g++) {
                uint32_t bh[4], bl[4];
                ldsm4(bh, sBh + boff[g] + kb);
                ldsm4(bl, sBl + boff[g] + kb);
#pragma unroll
                for (int sub = 0; sub < 2; sub++) {
                    const int nf = g * 2 + sub;
                    const uint32_t bh0 = bh[sub * 2], bh1 = bh[sub * 2 + 1];
                    const uint32_t bl0 = bl[sub * 2], bl1 = bl[sub * 2 + 1];
#pragma unroll
                    for (int mf = 0; mf < 2; mf++) {
                        mma_bf16(d[mf][nf], ah[mf], bh0, bh1);
                        mma_bf16(d[mf][nf], ah[mf], bl0, bl1);
                        mma_bf16(d[mf][nf], al[mf], bh0, bh1);
                    }
                }
            }
        }

        stg++; if (stg >= NSTAGE) stg = 0;
    }
}

// ---------------------------------------------------------------------------
// Merged QKV projection GEMM. blockIdx.z in {0,1,2} selects {Q,K,V}.
// z<2: out = bias+hi/lo split, row-major [NTOK, DDIM].
// z=2: out transposed [DDIM, NTOK].
// ---------------------------------------------------------------------------
__global__ void __launch_bounds__(256)
proj_gemm(const __nv_bfloat16* __restrict__ qh, const __nv_bfloat16* __restrict__ ql,
          const __nv_bfloat16* __restrict__ kh, const __nv_bfloat16* __restrict__ kl,
          const __nv_bfloat16* __restrict__ vh, const __nv_bfloat16* __restrict__ vl,
          const __nv_bfloat16* __restrict__ wqh, const __nv_bfloat16* __restrict__ wql,
          const __nv_bfloat16* __restrict__ wkh, const __nv_bfloat16* __restrict__ wkl,
          const __nv_bfloat16* __restrict__ wvh, const __nv_bfloat16* __restrict__ wvl,
          const float* __restrict__ bq, const float* __restrict__ bk,
          const float* __restrict__ bv,
          __nv_bfloat16* __restrict__ qph, __nv_bfloat16* __restrict__ qpl,
          __nv_bfloat16* __restrict__ kph, __nv_bfloat16* __restrict__ kpl,
          __nv_bfloat16* __restrict__ vpth, __nv_bfloat16* __restrict__ vptl)
{
    extern __shared__ char smem[];
    const uint32_t sbase = smem_u32(smem);
    const int tid = threadIdx.x;
    const int wid = tid >> 5, lane = tid & 31;
    const int wm = wid & 3, wn = wid >> 2;
    const int mBase = blockIdx.y * 128;
    const int nBase = blockIdx.x * 128;
    const int z = blockIdx.z;

    const __nv_bfloat16* Ah = (z == 0) ? qh : (z == 1) ? kh : vh;
    const __nv_bfloat16* Al = (z == 0) ? ql : (z == 1) ? kl : vl;
    const __nv_bfloat16* Bh = (z == 0) ? wqh : (z == 1) ? wkh : wvh;
    const __nv_bfloat16* Bl = (z == 0) ? wql : (z == 1) ? wkl : wvl;
    const float* bias = (z == 0) ? bq : (z == 1) ? bk : bv;
    __nv_bfloat16* Ch = (z == 0) ? qph : (z == 1) ? kph : vpth;
    __nv_bfloat16* Cl = (z == 0) ? qpl : (z == 1) ? kpl : vptl;

    float d[2][8][4];
#pragma unroll
    for (int i = 0; i < 2; i++)
#pragma unroll
        for (int j = 0; j < 8; j++)
#pragma unroll
            for (int e = 0; e < 4; e++) d[i][j][e] = 0.f;

    gemm_mainloop(Ah + (size_t)mBase * IDIM, Al + (size_t)mBase * IDIM,
                  Bh + (size_t)nBase * IDIM, Bl + (size_t)nBase * IDIM,
                  IDIM, IDIM, IDIM, sbase, tid, wm, wn, lane, d);

    const int row0 = mBase + wm * 32 + (lane >> 2);
    const int col0 = nBase + wn * 64 + (lane & 3) * 2;

#pragma unroll
    for (int mf = 0; mf < 2; mf++) {
#pragma unroll
        for (int nf = 0; nf < 8; nf++) {
            const int r = row0 + mf * 16;
            const int c = col0 + nf * 8;
            const float* dd = d[mf][nf];
            const float b0v = bias[c], b1v = bias[c + 1];
#pragma unroll
            for (int h = 0; h < 2; h++) {
                float v0 = dd[h * 2 + 0] + b0v;
                float v1 = dd[h * 2 + 1] + b1v;
                __nv_bfloat16 h0 = __float2bfloat16(v0);
                __nv_bfloat16 h1 = __float2bfloat16(v1);
                __nv_bfloat16 l0 = __float2bfloat16(v0 - __bfloat162float(h0));
                __nv_bfloat16 l1 = __float2bfloat16(v1 - __bfloat162float(h1));
                int rr = r + h * 8;
                if (z != 2) {
                    size_t o = (size_t)rr * DDIM + c;
                    *(__nv_bfloat162*)(Ch + o) = __nv_bfloat162(h0, h1);
                    *(__nv_bfloat162*)(Cl + o) = __nv_bfloat162(l0, l1);
                } else {
                    Ch[(size_t)c * NTOK + rr] = h0;
                    Cl[(size_t)c * NTOK + rr] = l0;
                    Ch[(size_t)(c + 1) * NTOK + rr] = h1;
                    Cl[(size_t)(c + 1) * NTOK + rr] = l1;
                }
            }
        }
    }
}

// ---------------------------------------------------------------------------
// Generic NT GEMM with fp32 output (logits & AV), batched via strides.
// ---------------------------------------------------------------------------
__global__ void __launch_bounds__(256)
hmma_gemm_f32(const __nv_bfloat16* __restrict__ Ah, const __nv_bfloat16* __restrict__ Al,
              const __nv_bfloat16* __restrict__ Bh, const __nv_bfloat16* __restrict__ Bl,
              float* __restrict__ Cf,
              int K, int lda, int ldb, int ldc,
              size_t sA, size_t sB, size_t sC)
{
    extern __shared__ char smem[];
    const uint32_t sbase = smem_u32(smem);
    const int tid = threadIdx.x;
    const int wid = tid >> 5, lane = tid & 31;
    const int wm = wid & 3, wn = wid >> 2;
    const int mBase = blockIdx.y * 128;
    const int nBase = blockIdx.x * 128;
    const int z = blockIdx.z;

    float d[2][8][4];
#pragma unroll
    for (int i = 0; i < 2; i++)
#pragma unroll
        for (int j = 0; j < 8; j++)
#pragma unroll
            for (int e = 0; e < 4; e++) d[i][j][e] = 0.f;

    gemm_mainloop(Ah + z * sA + (size_t)mBase * lda, Al + z * sA + (size_t)mBase * lda,
                  Bh + z * sB + (size_t)nBase * ldb, Bl + z * sB + (size_t)nBase * ldb,
                  K, lda, ldb, sbase, tid, wm, wn, lane, d);

    const int row0 = mBase + wm * 32 + (lane >> 2);
    const int col0 = nBase + wn * 64 + (lane & 3) * 2;
    float* Cp = Cf + z * sC;

#pragma unroll
    for (int mf = 0; mf < 2; mf++) {
#pragma unroll
        for (int nf = 0; nf < 8; nf++) {
            const int r = row0 + mf * 16;
            const int c = col0 + nf * 8;
            const float* dd = d[mf][nf];
            *(float2*)(Cp + (size_t)r * ldc + c) = make_float2(dd[0], dd[1]);
            *(float2*)(Cp + (size_t)(r + 8) * ldc + c) = make_float2(dd[2], dd[3]);
        }
    }
}

// ---------------------------------------------------------------------------
// fp32 -> (hi, lo) bf16 split; grid.y selects among 3 tensors
// ---------------------------------------------------------------------------
__global__ void __launch_bounds__(256)
split_f32_3(const float4* __restrict__ x0, __nv_bfloat16* __restrict__ h0p, __nv_bfloat16* __restrict__ l0p,
            const float4* __restrict__ x1, __nv_bfloat16* __restrict__ h1p, __nv_bfloat16* __restrict__ l1p,
            const float4* __restrict__ x2, __nv_bfloat16* __restrict__ h2p, __nv_bfloat16* __restrict__ l2p,
            int n4)
{
    int i = blockIdx.x * 256 + threadIdx.x;
    if (i >= n4) return;
    int s = blockIdx.y;
    const float4* x = (s == 0) ? x0 : (s == 1) ? x1 : x2;
    __nv_bfloat16* hi = (s == 0) ? h0p : (s == 1) ? h1p : h2p;
    __nv_bfloat16* lo = (s == 0) ? l0p : (s == 1) ? l1p : l2p;

    float4 v = x[i];
    float vv[4] = {v.x, v.y, v.z, v.w};
    __nv_bfloat162 h2[2], l2[2];
#pragma unroll
    for (int j = 0; j < 4; j++) {
        __nv_bfloat16 h = __float2bfloat16(vv[j]);
        __nv_bfloat16 l = __float2bfloat16(vv[j] - __bfloat162float(h));
        ((__nv_bfloat16*)h2)[j] = h;
        ((__nv_bfloat16*)l2)[j] = l;
    }
    ((__nv_bfloat162*)hi)[i * 2]     = h2[0];
    ((__nv_bfloat162*)hi)[i * 2 + 1] = h2[1];
    ((__nv_bfloat162*)lo)[i * 2]     = l2[0];
    ((__nv_bfloat162*)lo)[i * 2 + 1] = l2[1];
}

// W[K,N] fp32 -> WT hi/lo [N,K] bf16
__global__ void __launch_bounds__(256)
transpose_split(const float* __restrict__ W, __nv_bfloat16* __restrict__ Th,
                __nv_bfloat16* __restrict__ Tl, int rows, int cols)
{
    __shared__ float tile[32][33];
    int bx = blockIdx.x * 32;  // n
    int by = blockIdx.y * 32;  // k
    int tx = threadIdx.x & 31;
    int ty = threadIdx.x >> 5; // 0..7
#pragma unroll
    for (int i = ty; i < 32; i += 8)
        tile[i][tx] = W[(size_t)(by + i) * cols + bx + tx];
    __syncthreads();
#pragma unroll
    for (int i = ty; i < 32; i += 8) {
        float v = tile[tx][i];  // = W[by+tx][bx+i]
        __nv_bfloat16 h = __float2bfloat16(v);
        __nv_bfloat16 l = __float2bfloat16(v - __bfloat162float(h));
        size_t o = (size_t)(bx + i) * rows + by + tx;
        Th[o] = h;
        Tl[o] = l;
    }
}

// ---------------------------------------------------------------------------
// scale+mask+softmax, fp32 logits in -> bf16 hi/lo attn out
// ---------------------------------------------------------------------------
__global__ void __launch_bounds__(256)
softmax_split(const float* __restrict__ logits, const float* __restrict__ mask,
              __nv_bfloat16* __restrict__ ah, __nv_bfloat16* __restrict__ al,
              float scale)
{
    __shared__ float red[8];
    __shared__ float bval;

    size_t row = blockIdx.x;
    int q = (int)(row & (SDIM - 1));
    const float* rp = logits + row * (size_t)SDIM;
    const float* mp = mask + (size_t)q * SDIM;
    int t = threadIdx.x;

    float4 a = ((const float4*)rp)[t];
    float4 b = ((const float4*)rp)[t + 256];
    float4 ma = ((const float4*)mp)[t];
    float4 mb = ((const float4*)mp)[t + 256];
    float x[8];
    x[0] = fmaf(a.x, scale, ma.x); x[1] = fmaf(a.y, scale, ma.y);
    x[2] = fmaf(a.z, scale, ma.z); x[3] = fmaf(a.w, scale, ma.w);
    x[4] = fmaf(b.x, scale, mb.x); x[5] = fmaf(b.y, scale, mb.y);
    x[6] = fmaf(b.z, scale, mb.z); x[7] = fmaf(b.w, scale, mb.w);

    float mx = x[0];
#pragma unroll
    for (int i = 1; i < 8; i++) mx = fmaxf(mx, x[i]);
#pragma unroll
    for (int o = 16; o; o >>= 1) mx = fmaxf(mx, __shfl_xor_sync(0xffffffffu, mx, o));
    if ((t & 31) == 0) red[t >> 5] = mx;
    __syncthreads();
    if (t == 0) {
        float m = red[0];
#pragma unroll
        for (int i = 1; i < 8; i++) m = fmaxf(m, red[i]);
        bval = m;
    }
    __syncthreads();
    mx = bval;

    float s = 0.f;
#pragma unroll
    for (int i = 0; i < 8; i++) { x[i] = __expf(x[i] - mx); s += x[i]; }
#pragma unroll
    for (int o = 16; o; o >>= 1) s += __shfl_xor_sync(0xffffffffu, s, o);
    if ((t & 31) == 0) red[t >> 5] = s;
    __syncthreads();
    if (t == 0) {
        float ss = 0.f;
#pragma unroll
        for (int i = 0; i < 8; i++) ss += red[i];
        bval = 1.f / ss;
    }
    __syncthreads();
    float inv = bval;

    __nv_bfloat162* ah2 = (__nv_bfloat162*)(ah + row * (size_t)SDIM);
    __nv_bfloat162* al2 = (__nv_bfloat162*)(al + row * (size_t)SDIM);
#pragma unroll
    for (int half = 0; half < 2; half++) {
#pragma unroll
        for (int p = 0; p < 2; p++) {
            float p0 = x[half * 4 + p * 2 + 0] * inv;
            float p1 = x[half * 4 + p * 2 + 1] * inv;
            __nv_bfloat16 h0 = __float2bfloat16(p0);
            __nv_bfloat16 h1 = __float2bfloat16(p1);
            __nv_bfloat16 l0 = __float2bfloat16(p0 - __bfloat162float(h0));
            __nv_bfloat16 l1 = __float2bfloat16(p1 - __bfloat162float(h1));
            int idx = half * 512 + t * 2 + p;
            ah2[idx] = __nv_bfloat162(h0, h1);
            al2[idx] = __nv_bfloat162(l0, l1);
        }
    }
}

// ---------------------------------------------------------------------------
extern "C" void kernel_launch(void* const* d_in, const int* in_sizes, int n_in,
                              void* d_out, int out_size)
{
    const float* q    = (const float*)d_in[0];
    const float* k    = (const float*)d_in[1];
    const float* v    = (const float*)d_in[2];
    const float* mask = (const float*)d_in[3];
    const float* wq   = (const float*)d_in[4];
    const float* bq   = (const float*)d_in[5];
    const float* wk   = (const float*)d_in[6];
    const float* bk   = (const float*)d_in[7];
    const float* wv   = (const float*)d_in[8];
    const float* bv   = (const float*)d_in[9];
    float* out = (float*)d_out;

#define SYM(p, s) do { void* _t; cudaGetSymbolAddress(&_t, s); p = (decltype(p))_t; } while (0)
    __nv_bfloat16 *qh, *ql, *kh, *kl, *vh, *vl;
    __nv_bfloat16 *wqth, *wqtl, *wkth, *wktl, *wvth, *wvtl;
    __nv_bfloat16 *qph, *qpl, *kph, *kpl, *vpth, *vptl, *ah, *al;
    float* lg;
    SYM(qh, g_qh); SYM(ql, g_ql); SYM(kh, g_kh); SYM(kl, g_kl);
    SYM(vh, g_vh); SYM(vl, g_vl);
    SYM(wqth, g_wqt_h); SYM(wqtl, g_wqt_l);
    SYM(wkth, g_wkt_h); SYM(wktl, g_wkt_l);
    SYM(wvth, g_wvt_h); SYM(wvtl, g_wvt_l);
    SYM(qph, g_qph); SYM(qpl, g_qpl); SYM(kph, g_kph); SYM(kpl, g_kpl);
    SYM(vpth, g_vpth); SYM(vptl, g_vptl);
    SYM(ah, g_ah); SYM(al, g_al);
    SYM(lg, g_logits);
#undef SYM

    cudaFuncSetAttribute(proj_gemm, cudaFuncAttributeMaxDynamicSharedMemorySize, SMEM_TOTAL);
    cudaFuncSetAttribute(hmma_gemm_f32, cudaFuncAttributeMaxDynamicSharedMemorySize, SMEM_TOTAL);

    const int n4 = NTOK * IDIM / 4;
    dim3 tg(IDIM / 32, IDIM / 32);

    // 1: merged hi/lo split of q, k, v
    split_f32_3<<<dim3(n4 / 256, 3), 256>>>((const float4*)q, qh, ql,
                                            (const float4*)k, kh, kl,
                                            (const float4*)v, vh, vl, n4);
    // 2-4: weight transpose+split
    transpose_split<<<tg, 256>>>(wq, wqth, wqtl, IDIM, DDIM);
    transpose_split<<<tg, 256>>>(wk, wkth, wktl, IDIM, DDIM);
    transpose_split<<<tg, 256>>>(wv, wvth, wvtl, IDIM, DDIM);

    // 5: merged QKV projections (z selects operand set; z=2 writes vp^T)
    dim3 gp(DDIM / 128, NTOK / 128, 3);
    proj_gemm<<<gp, 256, SMEM_TOTAL>>>(qh, ql, kh, kl, vh, vl,
                                       wqth, wqtl, wkth, wktl, wvth, wvtl,
                                       bq, bk, bv,
                                       qph, qpl, kph, kpl, vpth, vptl);

    // 6: logits = qp @ kp^T (batched over B)
    dim3 gl(SDIM / 128, SDIM / 128, BDIM);
    hmma_gemm_f32<<<gl, 256, SMEM_TOTAL>>>(qph, qpl, kph, kpl, lg,
                                           DDIM, DDIM, DDIM, SDIM,
                                           (size_t)SDIM * DDIM, (size_t)SDIM * DDIM,
                                           (size_t)SDIM * SDIM);

    // 7: softmax -> attn hi/lo
    softmax_split<<<BDIM * SDIM, 256>>>(lg, mask, ah, al, 0.03125f);

    // 8: out = attn @ vp (B operand = vp^T, batch offset = column shift)
    dim3 ga(DDIM / 128, SDIM / 128, BDIM);
    hmma_gemm_f32<<<ga, 256, SMEM_TOTAL>>>(ah, al, vpth, vptl, out,
                                           SDIM, SDIM, NTOK, DDIM,
                                           (size_t)SDIM * SDIM, (size_t)SDIM,
                                           (size_t)SDIM * DDIM);
}

// round 6
// speedup vs baseline: 2.6854x; 1.0300x over previous
#include <cuda_runtime.h>
#include <cuda_bf16.h>
#include <cstdint>

#define BDIM 4
#define SDIM 2048
#define IDIM 1024
#define DDIM 1024
#define NTOK (BDIM * SDIM)   // 8192

// ---------------------------------------------------------------------------
// Device scratch (allocation-free rule)
// ---------------------------------------------------------------------------
__device__ __align__(128) __nv_bfloat16 g_qh[(size_t)NTOK * IDIM];
__device__ __align__(128) __nv_bfloat16 g_ql[(size_t)NTOK * IDIM];
__device__ __align__(128) __nv_bfloat16 g_kh[(size_t)NTOK * IDIM];
__device__ __align__(128) __nv_bfloat16 g_kl[(size_t)NTOK * IDIM];
__device__ __align__(128) __nv_bfloat16 g_vh[(size_t)NTOK * IDIM];
__device__ __align__(128) __nv_bfloat16 g_vl[(size_t)NTOK * IDIM];
__device__ __align__(128) __nv_bfloat16 g_wqt_h[(size_t)DDIM * IDIM];
__device__ __align__(128) __nv_bfloat16 g_wqt_l[(size_t)DDIM * IDIM];
__device__ __align__(128) __nv_bfloat16 g_wkt_h[(size_t)DDIM * IDIM];
__device__ __align__(128) __nv_bfloat16 g_wkt_l[(size_t)DDIM * IDIM];
__device__ __align__(128) __nv_bfloat16 g_wvt_h[(size_t)DDIM * IDIM];
__device__ __align__(128) __nv_bfloat16 g_wvt_l[(size_t)DDIM * IDIM];
__device__ __align__(128) __nv_bfloat16 g_qph[(size_t)NTOK * DDIM];
__device__ __align__(128) __nv_bfloat16 g_qpl[(size_t)NTOK * DDIM];
__device__ __align__(128) __nv_bfloat16 g_kph[(size_t)NTOK * DDIM];
__device__ __align__(128) __nv_bfloat16 g_kpl[(size_t)NTOK * DDIM];
__device__ __align__(128) __nv_bfloat16 g_vpth[(size_t)DDIM * NTOK];  // [D, tokens]
__device__ __align__(128) __nv_bfloat16 g_vptl[(size_t)DDIM * NTOK];
__device__ __align__(128) float g_logits[(size_t)BDIM * SDIM * SDIM];
__device__ __align__(128) __nv_bfloat16 g_ah[(size_t)BDIM * SDIM * SDIM];
__device__ __align__(128) __nv_bfloat16 g_al[(size_t)BDIM * SDIM * SDIM];

// ---------------------------------------------------------------------------
// PTX helpers (no tcgen05 — harness compiles for compute_103 w/o 'a' features)
// ---------------------------------------------------------------------------
__device__ __forceinline__ uint32_t smem_u32(const void* p) {
    uint32_t a;
    asm("{ .reg .u64 t; cvta.to.shared.u64 t, %1; cvt.u32.u64 %0, t; }"
        : "=r"(a) : "l"(p));
    return a;
}

__device__ __forceinline__ void cp16(uint32_t d, const void* g) {
    asm volatile("cp.async.cg.shared.global [%0], [%1], 16;" :: "r"(d), "l"(g) : "memory");
}
#define CP_COMMIT() asm volatile("cp.async.commit_group;" ::: "memory")
#define CP_WAIT1()  asm volatile("cp.async.wait_group 1;" ::: "memory")

__device__ __forceinline__ void ldsm4(uint32_t* r, uint32_t addr) {
    asm volatile("ldmatrix.sync.aligned.m8n8.x4.shared.b16 {%0,%1,%2,%3}, [%4];"
        : "=r"(r[0]), "=r"(r[1]), "=r"(r[2]), "=r"(r[3]) : "r"(addr));
}

// mma.sync m16n8k16 bf16 -> fp32 accumulate
__device__ __forceinline__ void mma_bf16(float* d, const uint32_t* a,
                                         uint32_t b0, uint32_t b1) {
    asm volatile(
        "mma.sync.aligned.m16n8k16.row.col.f32.bf16.bf16.f32 "
        "{%0,%1,%2,%3}, {%4,%5,%6,%7}, {%8,%9}, {%0,%1,%2,%3};"
        : "+f"(d[0]), "+f"(d[1]), "+f"(d[2]), "+f"(d[3])
        : "r"(a[0]), "r"(a[1]), "r"(a[2]), "r"(a[3]), "r"(b0), "r"(b1));
}

// SMEM stage: 4 arrays of 128 rows x 144B pitch (128B = 64 bf16 data, K-tile 64)
#define KT 64
#define ROWB 144
#define ARR_BYTES (128 * ROWB)          // 18432
#define OFF_AH 0
#define OFF_AL ARR_BYTES
#define OFF_BH (2 * ARR_BYTES)
#define OFF_BL (3 * ARR_BYTES)
#define STG_BYTES (4 * ARR_BYTES)       // 73728
#define NSTAGE 3
#define SMEM_TOTAL (NSTAGE * STG_BYTES) // 221184

#define NTHREADS 512

__device__ __forceinline__ void load_arr(const __nv_bfloat16* __restrict__ G,
                                         int ldg, int kt, uint32_t dst, int tid) {
#pragma unroll
    for (int i = 0; i < 2; i++) {
        int idx = tid + i * NTHREADS;
        int row = idx >> 3;
        int c = idx & 7;
        cp16(dst + row * ROWB + c * 16, (const void*)(G + (size_t)row * ldg + kt + c * 8));
    }
}

// ---------------------------------------------------------------------------
// Shared mainloop: D[128,128] += A[128,K] * B[128,K]^T (NT, hi/lo 3-product).
// 16 warps (4 m-rows x 4 n-cols), warp tile 32x32.
// ---------------------------------------------------------------------------
__device__ __forceinline__ void gemm_mainloop(
    const __nv_bfloat16* __restrict__ Ahb, const __nv_bfloat16* __restrict__ Alb,
    const __nv_bfloat16* __restrict__ Bhb, const __nv_bfloat16* __restrict__ Blb,
    int K, int lda, int ldb,
    uint32_t sbase, int tid, int wm, int wn, int lane,
    float d[2][4][4])
{
    const int w8 = lane & 7, j8 = lane >> 3;
    int aoff[2], boff[2];
#pragma unroll
    for (int mf = 0; mf < 2; mf++)
        aoff[mf] = (wm * 32 + mf * 16 + w8 + 8 * (j8 & 1)) * ROWB + (j8 >> 1) * 16;
#pragma unroll
    for (int g = 0; g < 2; g++)
        boff[g] = (wn * 32 + g * 16 + w8 + 8 * (j8 >> 1)) * ROWB + (j8 & 1) * 16;

    const int T = K / KT;

    // preload stages 0,1
#pragma unroll
    for (int p = 0; p < 2; p++) {
        uint32_t b = sbase + p * STG_BYTES;
        load_arr(Ahb, lda, p * KT, b + OFF_AH, tid);
        load_arr(Alb, lda, p * KT, b + OFF_AL, tid);
        load_arr(Bhb, ldb, p * KT, b + OFF_BH, tid);
        load_arr(Blb, ldb, p * KT, b + OFF_BL, tid);
        CP_COMMIT();
    }

    int stg = 0;
    for (int t = 0; t < T; t++) {
        CP_WAIT1();            // stage t complete
        __syncthreads();

        // prefetch stage t+2 into slot (stg+2)%3 (consumed at t-1; barrier protects)
        if (t + 2 < T) {
            int ps = stg + 2; if (ps >= NSTAGE) ps -= NSTAGE;
            uint32_t pb = sbase + ps * STG_BYTES;
            const int kt = (t + 2) * KT;
            load_arr(Ahb, lda, kt, pb + OFF_AH, tid);
            load_arr(Alb, lda, kt, pb + OFF_AL, tid);
            load_arr(Bhb, ldb, kt, pb + OFF_BH, tid);
            load_arr(Blb, ldb, kt, pb + OFF_BL, tid);
        }
        CP_COMMIT();

        const uint32_t sb = sbase + stg * STG_BYTES;
        const uint32_t sAh = sb + OFF_AH;
        const uint32_t sAl = sb + OFF_AL;
        const uint32_t sBh = sb + OFF_BH;
        const uint32_t sBl = sb + OFF_BL;

#pragma unroll
        for (int ks = 0; ks < 4; ks++) {
            const int kb = ks * 32;   // 16 bf16 = 32 bytes per k-step
            uint32_t ah[2][4], al[2][4];
            ldsm4(ah[0], sAh + aoff[0] + kb);
            ldsm4(ah[1], sAh + aoff[1] + kb);
            ldsm4(al[0], sAl + aoff[0] + kb);
            ldsm4(al[1], sAl + aoff[1] + kb);
            uint32_t bh[2][4], bl[2][4];
            ldsm4(bh[0], sBh + boff[0] + kb);
            ldsm4(bh[1], sBh + boff[1] + kb);
            ldsm4(bl[0], sBl + boff[0] + kb);
            ldsm4(bl[1], sBl + boff[1] + kb);
#pragma unroll
            for (int g = 0; g < 2; g++) {
#pragma unroll
                for (int sub = 0; sub < 2; sub++) {
                    const int nf = g * 2 + sub;
                    const uint32_t bh0 = bh[g][sub * 2], bh1 = bh[g][sub * 2 + 1];
                    const uint32_t bl0 = bl[g][sub * 2], bl1 = bl[g][sub * 2 + 1];
                    // interleave across mf so adjacent MMAs hit independent accs
                    mma_bf16(d[0][nf], ah[0], bh0, bh1);
                    mma_bf16(d[1][nf], ah[1], bh0, bh1);
                    mma_bf16(d[0][nf], ah[0], bl0, bl1);
                    mma_bf16(d[1][nf], ah[1], bl0, bl1);
                    mma_bf16(d[0][nf], al[0], bh0, bh1);
                    mma_bf16(d[1][nf], al[1], bh0, bh1);
                }
            }
        }

        stg++; if (stg >= NSTAGE) stg = 0;
    }
}

// ---------------------------------------------------------------------------
// Merged QKV projection GEMM. blockIdx.z in {0,1,2} selects {Q,K,V}.
// z<2: out = bias+hi/lo split, row-major [NTOK, DDIM].
// z=2: out transposed [DDIM, NTOK].
// ---------------------------------------------------------------------------
__global__ void __launch_bounds__(NTHREADS)
proj_gemm(const __nv_bfloat16* __restrict__ qh, const __nv_bfloat16* __restrict__ ql,
          const __nv_bfloat16* __restrict__ kh, const __nv_bfloat16* __restrict__ kl,
          const __nv_bfloat16* __restrict__ vh, const __nv_bfloat16* __restrict__ vl,
          const __nv_bfloat16* __restrict__ wqh, const __nv_bfloat16* __restrict__ wql,
          const __nv_bfloat16* __restrict__ wkh, const __nv_bfloat16* __restrict__ wkl,
          const __nv_bfloat16* __restrict__ wvh, const __nv_bfloat16* __restrict__ wvl,
          const float* __restrict__ bq, const float* __restrict__ bk,
          const float* __restrict__ bv,
          __nv_bfloat16* __restrict__ qph, __nv_bfloat16* __restrict__ qpl,
          __nv_bfloat16* __restrict__ kph, __nv_bfloat16* __restrict__ kpl,
          __nv_bfloat16* __restrict__ vpth, __nv_bfloat16* __restrict__ vptl)
{
    extern __shared__ char smem[];
    const uint32_t sbase = smem_u32(smem);
    const int tid = threadIdx.x;
    const int wid = tid >> 5, lane = tid & 31;
    const int wm = wid & 3, wn = wid >> 2;
    const int mBase = blockIdx.y * 128;
    const int nBase = blockIdx.x * 128;
    const int z = blockIdx.z;

    const __nv_bfloat16* Ah = (z == 0) ? qh : (z == 1) ? kh : vh;
    const __nv_bfloat16* Al = (z == 0) ? ql : (z == 1) ? kl : vl;
    const __nv_bfloat16* Bh = (z == 0) ? wqh : (z == 1) ? wkh : wvh;
    const __nv_bfloat16* Bl = (z == 0) ? wql : (z == 1) ? wkl : wvl;
    const float* bias = (z == 0) ? bq : (z == 1) ? bk : bv;
    __nv_bfloat16* Ch = (z == 0) ? qph : (z == 1) ? kph : vpth;
    __nv_bfloat16* Cl = (z == 0) ? qpl : (z == 1) ? kpl : vptl;

    float d[2][4][4];
#pragma unroll
    for (int i = 0; i < 2; i++)
#pragma unroll
        for (int j = 0; j < 4; j++)
#pragma unroll
            for (int e = 0; e < 4; e++) d[i][j][e] = 0.f;

    gemm_mainloop(Ah + (size_t)mBase * IDIM, Al + (size_t)mBase * IDIM,
                  Bh + (size_t)nBase * IDIM, Bl + (size_t)nBase * IDIM,
                  IDIM, IDIM, IDIM, sbase, tid, wm, wn, lane, d);

    const int row0 = mBase + wm * 32 + (lane >> 2);
    const int col0 = nBase + wn * 32 + (lane & 3) * 2;

#pragma unroll
    for (int mf = 0; mf < 2; mf++) {
#pragma unroll
        for (int nf = 0; nf < 4; nf++) {
            const int r = row0 + mf * 16;
            const int c = col0 + nf * 8;
            const float* dd = d[mf][nf];
            const float b0v = bias[c], b1v = bias[c + 1];
#pragma unroll
            for (int h = 0; h < 2; h++) {
                float v0 = dd[h * 2 + 0] + b0v;
                float v1 = dd[h * 2 + 1] + b1v;
                __nv_bfloat16 h0 = __float2bfloat16(v0);
                __nv_bfloat16 h1 = __float2bfloat16(v1);
                __nv_bfloat16 l0 = __float2bfloat16(v0 - __bfloat162float(h0));
                __nv_bfloat16 l1 = __float2bfloat16(v1 - __bfloat162float(h1));
                int rr = r + h * 8;
                if (z != 2) {
                    size_t o = (size_t)rr * DDIM + c;
                    *(__nv_bfloat162*)(Ch + o) = __nv_bfloat162(h0, h1);
                    *(__nv_bfloat162*)(Cl + o) = __nv_bfloat162(l0, l1);
                } else {
                    Ch[(size_t)c * NTOK + rr] = h0;
                    Cl[(size_t)c * NTOK + rr] = l0;
                    Ch[(size_t)(c + 1) * NTOK + rr] = h1;
                    Cl[(size_t)(c + 1) * NTOK + rr] = l1;
                }
            }
        }
    }
}

// ---------------------------------------------------------------------------
// Generic NT GEMM with fp32 output (logits & AV), batched via strides.
// ---------------------------------------------------------------------------
__global__ void __launch_bounds__(NTHREADS)
hmma_gemm_f32(const __nv_bfloat16* __restrict__ Ah, const __nv_bfloat16* __restrict__ Al,
              const __nv_bfloat16* __restrict__ Bh, const __nv_bfloat16* __restrict__ Bl,
              float* __restrict__ Cf,
              int K, int lda, int ldb, int ldc,
              size_t sA, size_t sB, size_t sC)
{
    extern __shared__ char smem[];
    const uint32_t sbase = smem_u32(smem);
    const int tid = threadIdx.x;
    const int wid = tid >> 5, lane = tid & 31;
    const int wm = wid & 3, wn = wid >> 2;
    const int mBase = blockIdx.y * 128;
    const int nBase = blockIdx.x * 128;
    const int z = blockIdx.z;

    float d[2][4][4];
#pragma unroll
    for (int i = 0; i < 2; i++)
#pragma unroll
        for (int j = 0; j < 4; j++)
#pragma unroll
            for (int e = 0; e < 4; e++) d[i][j][e] = 0.f;

    gemm_mainloop(Ah + z * sA + (size_t)mBase * lda, Al + z * sA + (size_t)mBase * lda,
                  Bh + z * sB + (size_t)nBase * ldb, Bl + z * sB + (size_t)nBase * ldb,
                  K, lda, ldb, sbase, tid, wm, wn, lane, d);

    const int row0 = mBase + wm * 32 + (lane >> 2);
    const int col0 = nBase + wn * 32 + (lane & 3) * 2;
    float* Cp = Cf + z * sC;

#pragma unroll
    for (int mf = 0; mf < 2; mf++) {
#pragma unroll
        for (int nf = 0; nf < 4; nf++) {
            const int r = row0 + mf * 16;
            const int c = col0 + nf * 8;
            const float* dd = d[mf][nf];
            *(float2*)(Cp + (size_t)r * ldc + c) = make_float2(dd[0], dd[1]);
            *(float2*)(Cp + (size_t)(r + 8) * ldc + c) = make_float2(dd[2], dd[3]);
        }
    }
}

// ---------------------------------------------------------------------------
// fp32 -> (hi, lo) bf16 split; grid.y selects among 3 tensors
// ---------------------------------------------------------------------------
__global__ void __launch_bounds__(256)
split_f32_3(const float4* __restrict__ x0, __nv_bfloat16* __restrict__ h0p, __nv_bfloat16* __restrict__ l0p,
            const float4* __restrict__ x1, __nv_bfloat16* __restrict__ h1p, __nv_bfloat16* __restrict__ l1p,
            const float4* __restrict__ x2, __nv_bfloat16* __restrict__ h2p, __nv_bfloat16* __restrict__ l2p,
            int n4)
{
    int i = blockIdx.x * 256 + threadIdx.x;
    if (i >= n4) return;
    int s = blockIdx.y;
    const float4* x = (s == 0) ? x0 : (s == 1) ? x1 : x2;
    __nv_bfloat16* hi = (s == 0) ? h0p : (s == 1) ? h1p : h2p;
    __nv_bfloat16* lo = (s == 0) ? l0p : (s == 1) ? l1p : l2p;

    float4 v = x[i];
    float vv[4] = {v.x, v.y, v.z, v.w};
    __nv_bfloat162 h2[2], l2[2];
#pragma unroll
    for (int j = 0; j < 4; j++) {
        __nv_bfloat16 h = __float2bfloat16(vv[j]);
        __nv_bfloat16 l = __float2bfloat16(vv[j] - __bfloat162float(h));
        ((__nv_bfloat16*)h2)[j] = h;
        ((__nv_bfloat16*)l2)[j] = l;
    }
    ((__nv_bfloat162*)hi)[i * 2]     = h2[0];
    ((__nv_bfloat162*)hi)[i * 2 + 1] = h2[1];
    ((__nv_bfloat162*)lo)[i * 2]     = l2[0];
    ((__nv_bfloat162*)lo)[i * 2 + 1] = l2[1];
}

// Merged W[K,N] fp32 -> WT hi/lo [N,K] bf16 for all 3 weights (grid.z)
__global__ void __launch_bounds__(256)
transpose_split_3(const float* __restrict__ W0, __nv_bfloat16* __restrict__ T0h, __nv_bfloat16* __restrict__ T0l,
                  const float* __restrict__ W1, __nv_bfloat16* __restrict__ T1h, __nv_bfloat16* __restrict__ T1l,
                  const float* __restrict__ W2, __nv_bfloat16* __restrict__ T2h, __nv_bfloat16* __restrict__ T2l,
                  int rows, int cols)
{
    __shared__ float tile[32][33];
    int s = blockIdx.z;
    const float* W = (s == 0) ? W0 : (s == 1) ? W1 : W2;
    __nv_bfloat16* Th = (s == 0) ? T0h : (s == 1) ? T1h : T2h;
    __nv_bfloat16* Tl = (s == 0) ? T0l : (s == 1) ? T1l : T2l;

    int bx = blockIdx.x * 32;  // n
    int by = blockIdx.y * 32;  // k
    int tx = threadIdx.x & 31;
    int ty = threadIdx.x >> 5; // 0..7
#pragma unroll
    for (int i = ty; i < 32; i += 8)
        tile[i][tx] = W[(size_t)(by + i) * cols + bx + tx];
    __syncthreads();
#pragma unroll
    for (int i = ty; i < 32; i += 8) {
        float v = tile[tx][i];  // = W[by+tx][bx+i]
        __nv_bfloat16 h = __float2bfloat16(v);
        __nv_bfloat16 l = __float2bfloat16(v - __bfloat162float(h));
        size_t o = (size_t)(bx + i) * rows + by + tx;
        Th[o] = h;
        Tl[o] = l;
    }
}

// ---------------------------------------------------------------------------
// scale+mask+softmax, fp32 logits in -> bf16 hi/lo attn out
// ---------------------------------------------------------------------------
__global__ void __launch_bounds__(256)
softmax_split(const float* __restrict__ logits, const float* __restrict__ mask,
              __nv_bfloat16* __restrict__ ah, __nv_bfloat16* __restrict__ al,
              float scale)
{
    __shared__ float red[8];
    __shared__ float bval;

    size_t row = blockIdx.x;
    int q = (int)(row & (SDIM - 1));
    const float* rp = logits + row * (size_t)SDIM;
    const float* mp = mask + (size_t)q * SDIM;
    int t = threadIdx.x;

    float4 a = ((const float4*)rp)[t];
    float4 b = ((const float4*)rp)[t + 256];
    float4 ma = ((const float4*)mp)[t];
    float4 mb = ((const float4*)mp)[t + 256];
    float x[8];
    x[0] = fmaf(a.x, scale, ma.x); x[1] = fmaf(a.y, scale, ma.y);
    x[2] = fmaf(a.z, scale, ma.z); x[3] = fmaf(a.w, scale, ma.w);
    x[4] = fmaf(b.x, scale, mb.x); x[5] = fmaf(b.y, scale, mb.y);
    x[6] = fmaf(b.z, scale, mb.z); x[7] = fmaf(b.w, scale, mb.w);

    float mx = x[0];
#pragma unroll
    for (int i = 1; i < 8; i++) mx = fmaxf(mx, x[i]);
#pragma unroll
    for (int o = 16; o; o >>= 1) mx = fmaxf(mx, __shfl_xor_sync(0xffffffffu, mx, o));
    if ((t & 31) == 0) red[t >> 5] = mx;
    __syncthreads();
    if (t == 0) {
        float m = red[0];
#pragma unroll
        for (int i = 1; i < 8; i++) m = fmaxf(m, red[i]);
        bval = m;
    }
    __syncthreads();
    mx = bval;

    float s = 0.f;
#pragma unroll
    for (int i = 0; i < 8; i++) { x[i] = __expf(x[i] - mx); s += x[i]; }
#pragma unroll
    for (int o = 16; o; o >>= 1) s += __shfl_xor_sync(0xffffffffu, s, o);
    if ((t & 31) == 0) red[t >> 5] = s;
    __syncthreads();
    if (t == 0) {
        float ss = 0.f;
#pragma unroll
        for (int i = 0; i < 8; i++) ss += red[i];
        bval = 1.f / ss;
    }
    __syncthreads();
    float inv = bval;

    __nv_bfloat162* ah2 = (__nv_bfloat162*)(ah + row * (size_t)SDIM);
    __nv_bfloat162* al2 = (__nv_bfloat162*)(al + row * (size_t)SDIM);
#pragma unroll
    for (int half = 0; half < 2; half++) {
#pragma unroll
        for (int p = 0; p < 2; p++) {
            float p0 = x[half * 4 + p * 2 + 0] * inv;
            float p1 = x[half * 4 + p * 2 + 1] * inv;
            __nv_bfloat16 h0 = __float2bfloat16(p0);
            __nv_bfloat16 h1 = __float2bfloat16(p1);
            __nv_bfloat16 l0 = __float2bfloat16(p0 - __bfloat162float(h0));
            __nv_bfloat16 l1 = __float2bfloat16(p1 - __bfloat162float(h1));
            int idx = half * 512 + t * 2 + p;
            ah2[idx] = __nv_bfloat162(h0, h1);
            al2[idx] = __nv_bfloat162(l0, l1);
        }
    }
}

// ---------------------------------------------------------------------------
extern "C" void kernel_launch(void* const* d_in, const int* in_sizes, int n_in,
                              void* d_out, int out_size)
{
    const float* q    = (const float*)d_in[0];
    const float* k    = (const float*)d_in[1];
    const float* v    = (const float*)d_in[2];
    const float* mask = (const float*)d_in[3];
    const float* wq   = (const float*)d_in[4];
    const float* bq   = (const float*)d_in[5];
    const float* wk   = (const float*)d_in[6];
    const float* bk   = (const float*)d_in[7];
    const float* wv   = (const float*)d_in[8];
    const float* bv   = (const float*)d_in[9];
    float* out = (float*)d_out;

#define SYM(p, s) do { void* _t; cudaGetSymbolAddress(&_t, s); p = (decltype(p))_t; } while (0)
    __nv_bfloat16 *qh, *ql, *kh, *kl, *vh, *vl;
    __nv_bfloat16 *wqth, *wqtl, *wkth, *wktl, *wvth, *wvtl;
    __nv_bfloat16 *qph, *qpl, *kph, *kpl, *vpth, *vptl, *ah, *al;
    float* lg;
    SYM(qh, g_qh); SYM(ql, g_ql); SYM(kh, g_kh); SYM(kl, g_kl);
    SYM(vh, g_vh); SYM(vl, g_vl);
    SYM(wqth, g_wqt_h); SYM(wqtl, g_wqt_l);
    SYM(wkth, g_wkt_h); SYM(wktl, g_wkt_l);
    SYM(wvth, g_wvt_h); SYM(wvtl, g_wvt_l);
    SYM(qph, g_qph); SYM(qpl, g_qpl); SYM(kph, g_kph); SYM(kpl, g_kpl);
    SYM(vpth, g_vpth); SYM(vptl, g_vptl);
    SYM(ah, g_ah); SYM(al, g_al);
    SYM(lg, g_logits);
#undef SYM

    cudaFuncSetAttribute(proj_gemm, cudaFuncAttributeMaxDynamicSharedMemorySize, SMEM_TOTAL);
    cudaFuncSetAttribute(hmma_gemm_f32, cudaFuncAttributeMaxDynamicSharedMemorySize, SMEM_TOTAL);

    const int n4 = NTOK * IDIM / 4;

    // 1: merged hi/lo split of q, k, v
    split_f32_3<<<dim3(n4 / 256, 3), 256>>>((const float4*)q, qh, ql,
                                            (const float4*)k, kh, kl,
                                            (const float4*)v, vh, vl, n4);
    // 2: merged weight transpose+split
    transpose_split_3<<<dim3(IDIM / 32, IDIM / 32, 3), 256>>>(
        wq, wqth, wqtl, wk, wkth, wktl, wv, wvth, wvtl, IDIM, DDIM);

    // 3: merged QKV projections (z selects operand set; z=2 writes vp^T)
    dim3 gp(DDIM / 128, NTOK / 128, 3);
    proj_gemm<<<gp, NTHREADS, SMEM_TOTAL>>>(qh, ql, kh, kl, vh, vl,
                                            wqth, wqtl, wkth, wktl, wvth, wvtl,
                                            bq, bk, bv,
                                            qph, qpl, kph, kpl, vpth, vptl);

    // 4: logits = qp @ kp^T (batched over B)   <- ncu profiles this launch
    dim3 gl(SDIM / 128, SDIM / 128, BDIM);
    hmma_gemm_f32<<<gl, NTHREADS, SMEM_TOTAL>>>(qph, qpl, kph, kpl, lg,
                                                DDIM, DDIM, DDIM, SDIM,
                                                (size_t)SDIM * DDIM, (size_t)SDIM * DDIM,
                                                (size_t)SDIM * SDIM);

    // 5: softmax -> attn hi/lo
    softmax_split<<<BDIM * SDIM, 256>>>(lg, mask, ah, al, 0.03125f);

    // 6: out = attn @ vp (B operand = vp^T, batch offset = column shift)
    dim3 ga(DDIM / 128, SDIM / 128, BDIM);
    hmma_gemm_f32<<<ga, NTHREADS, SMEM_TOTAL>>>(ah, al, vpth, vptl, out,
                                                SDIM, SDIM, NTOK, DDIM,
                                                (size_t)SDIM * SDIM, (size_t)SDIM,
                                                (size_t)SDIM * DDIM);
}